// round 1
// baseline (speedup 1.0000x reference)
#include <cuda_runtime.h>
#include <math.h>

// ---------------------------------------------------------------------------
// Problem dims (fixed by the reference)
// ---------------------------------------------------------------------------
#define BB      16
#define SS      512
#define DMODEL  1024
#define NHEADS  16
#define DK      64
#define DFF     4096
#define MROWS   (BB * SS)          // 8192

// ---------------------------------------------------------------------------
// Scratch (device globals -> no allocation inside kernel_launch)
// ---------------------------------------------------------------------------
__device__ float g_ln1[MROWS * DMODEL];
__device__ float g_q  [MROWS * DMODEL];
__device__ float g_k  [MROWS * DMODEL];
__device__ float g_v  [MROWS * DMODEL];
__device__ float g_att[MROWS * DMODEL];
__device__ float g_x2 [MROWS * DMODEL];
__device__ float g_ln2[MROWS * DMODEL];
__device__ float g_ff [MROWS * DFF];

// ---------------------------------------------------------------------------
// LayerNorm: one block per row of 1024, 256 threads, float4 per thread
// ---------------------------------------------------------------------------
__global__ void __launch_bounds__(256) layernorm_kernel(
    const float* __restrict__ x, const float* __restrict__ g,
    const float* __restrict__ be, float* __restrict__ out)
{
    const int row = blockIdx.x;
    const int tid = threadIdx.x;
    const float4 v = *(const float4*)(x + (long)row * DMODEL + tid * 4);

    float s1 = v.x + v.y + v.z + v.w;
    float s2 = v.x * v.x + v.y * v.y + v.z * v.z + v.w * v.w;

    #pragma unroll
    for (int off = 16; off > 0; off >>= 1) {
        s1 += __shfl_xor_sync(0xffffffffu, s1, off);
        s2 += __shfl_xor_sync(0xffffffffu, s2, off);
    }
    __shared__ float sm1[8], sm2[8];
    const int w = tid >> 5, l = tid & 31;
    if (l == 0) { sm1[w] = s1; sm2[w] = s2; }
    __syncthreads();
    if (w == 0) {
        s1 = (l < 8) ? sm1[l] : 0.f;
        s2 = (l < 8) ? sm2[l] : 0.f;
        #pragma unroll
        for (int off = 4; off > 0; off >>= 1) {
            s1 += __shfl_xor_sync(0xffffffffu, s1, off);
            s2 += __shfl_xor_sync(0xffffffffu, s2, off);
        }
        if (l == 0) { sm1[0] = s1; sm2[0] = s2; }
    }
    __syncthreads();

    const float mu  = sm1[0] * (1.f / DMODEL);
    const float var = sm2[0] * (1.f / DMODEL) - mu * mu;
    const float inv = rsqrtf(var + 1e-5f);

    const float4 gv = *(const float4*)(g  + tid * 4);
    const float4 bv = *(const float4*)(be + tid * 4);
    float4 o;
    o.x = (v.x - mu) * inv * gv.x + bv.x;
    o.y = (v.y - mu) * inv * gv.y + bv.y;
    o.z = (v.z - mu) * inv * gv.z + bv.z;
    o.w = (v.w - mu) * inv * gv.w + bv.w;
    *(float4*)(out + (long)row * DMODEL + tid * 4) = o;
}

// ---------------------------------------------------------------------------
// SGEMM: C[M,N] = A[M,K] @ B[K,N]  (+bias)(relu)(+res), all dims % 128 == 0
// 128x128 block tile, BK=8, 256 threads, 8x8 per thread.
// ---------------------------------------------------------------------------
template<bool HAS_BIAS, bool DO_RELU, bool HAS_RES>
__global__ void __launch_bounds__(256) sgemm_kernel(
    const float* __restrict__ A, const float* __restrict__ B,
    const float* __restrict__ bias, const float* __restrict__ res,
    float* __restrict__ C, int M, int N, int K)
{
    __shared__ float As[8][132];
    __shared__ float Bs[8][128];

    const int tid = threadIdx.x;
    const int bm = blockIdx.y * 128;
    const int bn = blockIdx.x * 128;
    const int tx = tid & 15;
    const int ty = tid >> 4;

    const int ar = tid >> 1;          // 0..127
    const int ac = (tid & 1) * 4;     // 0 or 4
    const int br = tid >> 5;          // 0..7
    const int bc = (tid & 31) * 4;    // 0..124

    const float* Ap = A + (long)(bm + ar) * K + ac;
    const float* Bp = B + (long)br * N + bn + bc;

    float acc[8][8];
    #pragma unroll
    for (int i = 0; i < 8; i++)
        #pragma unroll
        for (int j = 0; j < 8; j++) acc[i][j] = 0.f;

    for (int k0 = 0; k0 < K; k0 += 8) {
        const float4 a4 = *(const float4*)Ap;
        const float4 b4 = *(const float4*)Bp;
        Ap += 8;
        Bp += (long)8 * N;

        As[ac + 0][ar] = a4.x;
        As[ac + 1][ar] = a4.y;
        As[ac + 2][ar] = a4.z;
        As[ac + 3][ar] = a4.w;
        *(float4*)&Bs[br][bc] = b4;
        __syncthreads();

        #pragma unroll
        for (int kk = 0; kk < 8; kk++) {
            float a[8], b[8];
            *(float4*)&a[0] = *(const float4*)&As[kk][ty * 8];
            *(float4*)&a[4] = *(const float4*)&As[kk][ty * 8 + 4];
            *(float4*)&b[0] = *(const float4*)&Bs[kk][tx * 8];
            *(float4*)&b[4] = *(const float4*)&Bs[kk][tx * 8 + 4];
            #pragma unroll
            for (int i = 0; i < 8; i++)
                #pragma unroll
                for (int j = 0; j < 8; j++)
                    acc[i][j] = fmaf(a[i], b[j], acc[i][j]);
        }
        __syncthreads();
    }

    #pragma unroll
    for (int i = 0; i < 8; i++) {
        const int row = bm + ty * 8 + i;
        float* Cr = C + (long)row * N + bn + tx * 8;
        #pragma unroll
        for (int j4 = 0; j4 < 8; j4 += 4) {
            float4 o;
            o.x = acc[i][j4 + 0];
            o.y = acc[i][j4 + 1];
            o.z = acc[i][j4 + 2];
            o.w = acc[i][j4 + 3];
            if (HAS_BIAS) {
                const float4 bb = *(const float4*)(bias + bn + tx * 8 + j4);
                o.x += bb.x; o.y += bb.y; o.z += bb.z; o.w += bb.w;
            }
            if (DO_RELU) {
                o.x = fmaxf(o.x, 0.f); o.y = fmaxf(o.y, 0.f);
                o.z = fmaxf(o.z, 0.f); o.w = fmaxf(o.w, 0.f);
            }
            if (HAS_RES) {
                const float4 rr = *(const float4*)(res + (long)row * N + bn + tx * 8 + j4);
                o.x += rr.x; o.y += rr.y; o.z += rr.z; o.w += rr.w;
            }
            *(float4*)(Cr + j4) = o;
        }
    }
}

// ---------------------------------------------------------------------------
// Causal flash attention.
// Q/K/V layout: [b, s, h*64 + d] (row stride 1024).
// Block = 64 query rows of one (b,h). 256 threads: thread (tr,tc) owns a
// 4x4 chunk: rows 4tr..4tr+3, cols 4tc..4tc+3.
// smem: Qs[64][64] + Ks[64][65] (reused for P after S is computed) + Vs[64][64]
//      = 49408 bytes dynamic.
// ---------------------------------------------------------------------------
__global__ void __launch_bounds__(256) attention_kernel(
    const float* __restrict__ Q, const float* __restrict__ K,
    const float* __restrict__ V, float* __restrict__ O)
{
    extern __shared__ float smem[];
    float* Qs = smem;            // 64*64 = 4096
    float* Ks = smem + 4096;     // 64*65 = 4160 (reused as P)
    float* Vs = smem + 8256;     // 64*64 = 4096

    const int qt = blockIdx.x;          // 0..7 query tile
    const int bh = blockIdx.y;          // 0..255
    const int b  = bh >> 4;
    const int h  = bh & 15;
    const int q0 = qt * 64;
    const long base = (long)(b * SS) * DMODEL + h * DK;

    const int tid = threadIdx.x;
    const int tr = tid >> 4;            // 0..15
    const int tc = tid & 15;            // 0..15

    // load Q tile (pre-scaled by 1/sqrt(dk) = 0.125)
    for (int i = tid; i < 64 * 16; i += 256) {
        const int r  = i >> 4;
        const int d4 = (i & 15) * 4;
        const float4 qv = *(const float4*)(Q + base + (long)(q0 + r) * DMODEL + d4);
        Qs[r * 64 + d4 + 0] = qv.x * 0.125f;
        Qs[r * 64 + d4 + 1] = qv.y * 0.125f;
        Qs[r * 64 + d4 + 2] = qv.z * 0.125f;
        Qs[r * 64 + d4 + 3] = qv.w * 0.125f;
    }

    float m_st[4], l_st[4], o_acc[4][4];
    #pragma unroll
    for (int i = 0; i < 4; i++) {
        m_st[i] = -1e30f;
        l_st[i] = 0.f;
        #pragma unroll
        for (int j = 0; j < 4; j++) o_acc[i][j] = 0.f;
    }

    for (int kt = 0; kt <= qt; kt++) {
        __syncthreads();   // prev-iter P/V reads done; Q load done (first iter)
        for (int i = tid; i < 64 * 16; i += 256) {
            const int r  = i >> 4;
            const int d4 = (i & 15) * 4;
            const float4 kv = *(const float4*)(K + base + (long)(kt * 64 + r) * DMODEL + d4);
            Ks[r * 65 + d4 + 0] = kv.x;
            Ks[r * 65 + d4 + 1] = kv.y;
            Ks[r * 65 + d4 + 2] = kv.z;
            Ks[r * 65 + d4 + 3] = kv.w;
            const float4 vv = *(const float4*)(V + base + (long)(kt * 64 + r) * DMODEL + d4);
            *(float4*)&Vs[r * 64 + d4] = vv;
        }
        __syncthreads();

        // S = Q K^T  (4x4 per thread)
        float s[4][4];
        #pragma unroll
        for (int i = 0; i < 4; i++)
            #pragma unroll
            for (int j = 0; j < 4; j++) s[i][j] = 0.f;

        #pragma unroll 16
        for (int d = 0; d < 64; d++) {
            float qv[4], kv[4];
            #pragma unroll
            for (int i = 0; i < 4; i++) qv[i] = Qs[(4 * tr + i) * 64 + d];
            #pragma unroll
            for (int j = 0; j < 4; j++) kv[j] = Ks[(4 * tc + j) * 65 + d];
            #pragma unroll
            for (int i = 0; i < 4; i++)
                #pragma unroll
                for (int j = 0; j < 4; j++)
                    s[i][j] = fmaf(qv[i], kv[j], s[i][j]);
        }

        if (kt == qt) {  // diagonal tile: causal mask (key > query)
            #pragma unroll
            for (int i = 0; i < 4; i++)
                #pragma unroll
                for (int j = 0; j < 4; j++)
                    if (4 * tc + j > 4 * tr + i) s[i][j] = -1e30f;
        }

        // online softmax update (row reduce over 16 lanes sharing tr)
        #pragma unroll
        for (int i = 0; i < 4; i++) {
            float mt = fmaxf(fmaxf(s[i][0], s[i][1]), fmaxf(s[i][2], s[i][3]));
            #pragma unroll
            for (int off = 8; off > 0; off >>= 1)
                mt = fmaxf(mt, __shfl_xor_sync(0xffffffffu, mt, off));
            const float mnew = fmaxf(m_st[i], mt);
            float rs = 0.f;
            #pragma unroll
            for (int j = 0; j < 4; j++) {
                s[i][j] = __expf(s[i][j] - mnew);
                rs += s[i][j];
            }
            #pragma unroll
            for (int off = 8; off > 0; off >>= 1)
                rs += __shfl_xor_sync(0xffffffffu, rs, off);
            const float corr = __expf(m_st[i] - mnew);
            m_st[i] = mnew;
            l_st[i] = l_st[i] * corr + rs;
            #pragma unroll
            for (int j = 0; j < 4; j++) o_acc[i][j] *= corr;
        }

        __syncthreads();          // everyone done reading Ks (as K)
        #pragma unroll
        for (int i = 0; i < 4; i++)
            #pragma unroll
            for (int j = 0; j < 4; j++)
                Ks[(4 * tr + i) * 65 + 4 * tc + j] = s[i][j];   // P
        __syncthreads();

        // O += P @ V
        #pragma unroll 16
        for (int c = 0; c < 64; c++) {
            float pv[4], vv[4];
            #pragma unroll
            for (int i = 0; i < 4; i++) pv[i] = Ks[(4 * tr + i) * 65 + c];
            #pragma unroll
            for (int j = 0; j < 4; j++) vv[j] = Vs[c * 64 + 4 * tc + j];
            #pragma unroll
            for (int i = 0; i < 4; i++)
                #pragma unroll
                for (int j = 0; j < 4; j++)
                    o_acc[i][j] = fmaf(pv[i], vv[j], o_acc[i][j]);
        }
    }

    #pragma unroll
    for (int i = 0; i < 4; i++) {
        const float inv = 1.f / l_st[i];
        float4 o;
        o.x = o_acc[i][0] * inv;
        o.y = o_acc[i][1] * inv;
        o.z = o_acc[i][2] * inv;
        o.w = o_acc[i][3] * inv;
        *(float4*)(O + base + (long)(q0 + 4 * tr + i) * DMODEL + 4 * tc) = o;
    }
}

// ---------------------------------------------------------------------------
// Launch
// inputs: x, Wq, Wk, Wv, Wo, W1, b1, W2, b2, g1, be1, g2, be2
// ---------------------------------------------------------------------------
extern "C" void kernel_launch(void* const* d_in, const int* in_sizes, int n_in,
                              void* d_out, int out_size)
{
    const float* x   = (const float*)d_in[0];
    const float* Wq  = (const float*)d_in[1];
    const float* Wk  = (const float*)d_in[2];
    const float* Wv  = (const float*)d_in[3];
    const float* Wo  = (const float*)d_in[4];
    const float* W1  = (const float*)d_in[5];
    const float* b1  = (const float*)d_in[6];
    const float* W2  = (const float*)d_in[7];
    const float* b2  = (const float*)d_in[8];
    const float* g1  = (const float*)d_in[9];
    const float* be1 = (const float*)d_in[10];
    const float* g2  = (const float*)d_in[11];
    const float* be2 = (const float*)d_in[12];
    float* out = (float*)d_out;

    float *h1, *q, *k, *v, *att, *x2, *h2, *ff;
    cudaGetSymbolAddress((void**)&h1,  g_ln1);
    cudaGetSymbolAddress((void**)&q,   g_q);
    cudaGetSymbolAddress((void**)&k,   g_k);
    cudaGetSymbolAddress((void**)&v,   g_v);
    cudaGetSymbolAddress((void**)&att, g_att);
    cudaGetSymbolAddress((void**)&x2,  g_x2);
    cudaGetSymbolAddress((void**)&h2,  g_ln2);
    cudaGetSymbolAddress((void**)&ff,  g_ff);

    const int attn_smem = (64 * 64 + 64 * 65 + 64 * 64) * (int)sizeof(float); // 49408
    cudaFuncSetAttribute(attention_kernel,
                         cudaFuncAttributeMaxDynamicSharedMemorySize, attn_smem);

    // 1) LN1
    layernorm_kernel<<<MROWS, 256>>>(x, g1, be1, h1);

    // 2-4) Q, K, V projections
    {
        dim3 grid(DMODEL / 128, MROWS / 128);
        sgemm_kernel<false, false, false><<<grid, 256>>>(h1, Wq, nullptr, nullptr, q, MROWS, DMODEL, DMODEL);
        sgemm_kernel<false, false, false><<<grid, 256>>>(h1, Wk, nullptr, nullptr, k, MROWS, DMODEL, DMODEL);
        sgemm_kernel<false, false, false><<<grid, 256>>>(h1, Wv, nullptr, nullptr, v, MROWS, DMODEL, DMODEL);
    }

    // 5) causal attention
    {
        dim3 grid(SS / 64, BB * NHEADS);
        attention_kernel<<<grid, 256, attn_smem>>>(q, k, v, att);
    }

    // 6) output projection + residual (x)
    {
        dim3 grid(DMODEL / 128, MROWS / 128);
        sgemm_kernel<false, false, true><<<grid, 256>>>(att, Wo, nullptr, x, x2, MROWS, DMODEL, DMODEL);
    }

    // 7) LN2
    layernorm_kernel<<<MROWS, 256>>>(x2, g2, be2, h2);

    // 8) FFN1: relu(h2 @ W1 + b1)
    {
        dim3 grid(DFF / 128, MROWS / 128);
        sgemm_kernel<true, true, false><<<grid, 256>>>(h2, W1, b1, nullptr, ff, MROWS, DFF, DMODEL);
    }

    // 9) FFN2: x2 + ff @ W2 + b2  -> out
    {
        dim3 grid(DMODEL / 128, MROWS / 128);
        sgemm_kernel<true, false, true><<<grid, 256>>>(ff, W2, b2, x2, out, MROWS, DMODEL, DFF);
    }
}

// round 4
// speedup vs baseline: 2.1661x; 2.1661x over previous
#include <cuda_runtime.h>
#include <cuda_bf16.h>
#include <cstdint>
#include <math.h>

// ---------------------------------------------------------------------------
// Problem dims
// ---------------------------------------------------------------------------
#define BB      16
#define SS      512
#define DMODEL  1024
#define NHEADS  16
#define DK      64
#define DFF     4096
#define MROWS   (BB * SS)          // 8192
#define MEG     (1024 * 1024)

// ---------------------------------------------------------------------------
// Scratch (device globals)
// ---------------------------------------------------------------------------
__device__ float g_q  [MROWS * DMODEL];
__device__ float g_k  [MROWS * DMODEL];
__device__ float g_v  [MROWS * DMODEL];
__device__ float g_x2 [MROWS * DMODEL];
__device__ __nv_bfloat16 g_a_hi[MROWS * DMODEL];   // activations (ln1 / att / ln2)
__device__ __nv_bfloat16 g_a_lo[MROWS * DMODEL];
__device__ __nv_bfloat16 g_f_hi[MROWS * DFF];      // ffn intermediate
__device__ __nv_bfloat16 g_f_lo[MROWS * DFF];
__device__ __nv_bfloat16 g_w_hi[12 * MEG];         // transposed weights (hi)
__device__ __nv_bfloat16 g_w_lo[12 * MEG];         // transposed weights (lo)
// offsets: Wq=0, Wk=1M, Wv=2M, Wo=3M, W1t=4M(4M), W2t=8M(4M)

// single extern dynamic-smem symbol
extern __shared__ char smem_raw[];

// ---------------------------------------------------------------------------
// PTX helpers (baseline features only: cp.async, ldmatrix, mma.sync)
// ---------------------------------------------------------------------------
__device__ __forceinline__ uint32_t smem_u32(const void* p) {
    uint32_t a;
    asm("{ .reg .u64 t; cvta.to.shared.u64 t, %1; cvt.u32.u64 %0, t; }"
        : "=r"(a) : "l"(p));
    return a;
}
#define CP_ASYNC16(dst, src) \
    asm volatile("cp.async.cg.shared.global [%0], [%1], 16;" :: "r"(dst), "l"(src))
#define CP_COMMIT() asm volatile("cp.async.commit_group;" ::: "memory")
#define CP_WAIT(n)  asm volatile("cp.async.wait_group %0;" :: "n"(n) : "memory")

#define LDMATRIX_X4(r0, r1, r2, r3, addr) \
    asm volatile("ldmatrix.sync.aligned.m8n8.x4.shared.b16 {%0,%1,%2,%3}, [%4];" \
                 : "=r"(r0), "=r"(r1), "=r"(r2), "=r"(r3) : "r"(addr))

#define MMA_BF16(c0, c1, c2, c3, a0, a1, a2, a3, b0, b1) \
    asm volatile("mma.sync.aligned.m16n8k16.row.col.f32.bf16.bf16.f32 " \
                 "{%0,%1,%2,%3}, {%4,%5,%6,%7}, {%8,%9}, {%0,%1,%2,%3};" \
                 : "+f"(c0), "+f"(c1), "+f"(c2), "+f"(c3) \
                 : "r"(a0), "r"(a1), "r"(a2), "r"(a3), "r"(b0), "r"(b1))

__device__ __forceinline__ __nv_bfloat16 bf_hi(float v) { return __float2bfloat16(v); }
__device__ __forceinline__ __nv_bfloat16 bf_lo(float v, __nv_bfloat16 h) {
    return __float2bfloat16(v - __bfloat162float(h));
}

// ---------------------------------------------------------------------------
// Weight transpose + bf16 split:  W[K][N] fp32  ->  out_hi/out_lo [N][K] bf16
// ---------------------------------------------------------------------------
__global__ void __launch_bounds__(256) transpose_split_kernel(
    const float* __restrict__ W, __nv_bfloat16* __restrict__ oh,
    __nv_bfloat16* __restrict__ ol, int K, int N)
{
    __shared__ float t[32][33];
    const int tx = threadIdx.x, ty = threadIdx.y;   // 32 x 8
    const int n0 = blockIdx.x * 32;
    const int k0 = blockIdx.y * 32;
    #pragma unroll
    for (int j = 0; j < 32; j += 8)
        t[ty + j][tx] = W[(size_t)(k0 + ty + j) * N + n0 + tx];
    __syncthreads();
    #pragma unroll
    for (int j = 0; j < 32; j += 8) {
        const float v = t[tx][ty + j];
        const __nv_bfloat16 h = bf_hi(v);
        const size_t idx = (size_t)(n0 + ty + j) * K + k0 + tx;
        oh[idx] = h;
        ol[idx] = bf_lo(v, h);
    }
}

// ---------------------------------------------------------------------------
// LayerNorm -> bf16 hi/lo split
// ---------------------------------------------------------------------------
__global__ void __launch_bounds__(256) layernorm_split_kernel(
    const float* __restrict__ x, const float* __restrict__ g,
    const float* __restrict__ be, __nv_bfloat16* __restrict__ oh,
    __nv_bfloat16* __restrict__ ol)
{
    const int row = blockIdx.x;
    const int tid = threadIdx.x;
    const float4 v = *(const float4*)(x + (size_t)row * DMODEL + tid * 4);

    float s1 = v.x + v.y + v.z + v.w;
    float s2 = v.x * v.x + v.y * v.y + v.z * v.z + v.w * v.w;
    #pragma unroll
    for (int off = 16; off > 0; off >>= 1) {
        s1 += __shfl_xor_sync(0xffffffffu, s1, off);
        s2 += __shfl_xor_sync(0xffffffffu, s2, off);
    }
    __shared__ float sm1[8], sm2[8];
    const int w = tid >> 5, l = tid & 31;
    if (l == 0) { sm1[w] = s1; sm2[w] = s2; }
    __syncthreads();
    if (w == 0) {
        s1 = (l < 8) ? sm1[l] : 0.f;
        s2 = (l < 8) ? sm2[l] : 0.f;
        #pragma unroll
        for (int off = 4; off > 0; off >>= 1) {
            s1 += __shfl_xor_sync(0xffffffffu, s1, off);
            s2 += __shfl_xor_sync(0xffffffffu, s2, off);
        }
        if (l == 0) { sm1[0] = s1; sm2[0] = s2; }
    }
    __syncthreads();

    const float mu  = sm1[0] * (1.f / DMODEL);
    const float var = sm2[0] * (1.f / DMODEL) - mu * mu;
    const float inv = rsqrtf(var + 1e-5f);

    const float4 gv = *(const float4*)(g  + tid * 4);
    const float4 bv = *(const float4*)(be + tid * 4);
    float o[4];
    o[0] = (v.x - mu) * inv * gv.x + bv.x;
    o[1] = (v.y - mu) * inv * gv.y + bv.y;
    o[2] = (v.z - mu) * inv * gv.z + bv.z;
    o[3] = (v.w - mu) * inv * gv.w + bv.w;

    __align__(8) __nv_bfloat16 h4[4], l4[4];
    #pragma unroll
    for (int j = 0; j < 4; j++) { h4[j] = bf_hi(o[j]); l4[j] = bf_lo(o[j], h4[j]); }
    const size_t idx = (size_t)row * DMODEL + tid * 4;
    *(uint2*)(oh + idx) = *(uint2*)h4;
    *(uint2*)(ol + idx) = *(uint2*)l4;
}

// ---------------------------------------------------------------------------
// mma.sync bf16 split-3 GEMM:  C[M,N] = (Ah+Al)[M,K] @ (Bh+Bl)^T[N,K]
//   terms: Ah*Bh + Ah*Bl + Al*Bh  (K_eff = 3K, folded into one loop)
// CTA tile 128x128, BK=64, 2-stage cp.async pipeline, smem rows padded to 72.
// 8 warps: warp_m = wid&3 (32 rows), warp_n = wid>>2 (64 cols).
// MODE: 0 = f32 out | 1 = +res | 2 = bf16 hi/lo relu(+bias) | 3 = +bias +res
// ---------------------------------------------------------------------------
#define SM_STRIDE 72                       // bf16 elements per smem row
#define STAGE_BYTES (128 * SM_STRIDE * 2 * 2)   // A + B per stage = 36864

template<int MODE>
__global__ void __launch_bounds__(256, 2) gemm_mma_kernel(
    const __nv_bfloat16* __restrict__ Ah, const __nv_bfloat16* __restrict__ Al,
    const __nv_bfloat16* __restrict__ Bh, const __nv_bfloat16* __restrict__ Bl,
    const float* __restrict__ bias, const float* __restrict__ res,
    float* __restrict__ Cf, __nv_bfloat16* __restrict__ Oh,
    __nv_bfloat16* __restrict__ Ol, int M, int N, int K)
{
    const uint32_t sbase = smem_u32(smem_raw);
    const int tid = threadIdx.x;
    const int wid = tid >> 5, lid = tid & 31;
    const int warp_m = wid & 3;           // 0..3  (32-row slices)
    const int warp_n = wid >> 2;          // 0..1  (64-col slices)
    const int bm = blockIdx.y * 128;
    const int bn = blockIdx.x * 128;

    const __nv_bfloat16* PA[3] = { Ah, Ah, Al };
    const __nv_bfloat16* PB[3] = { Bh, Bl, Bh };

    const int segN = K >> 6;              // chunks per split term
    const int NCC  = 3 * segN;            // total K-chunks

    auto load_chunk = [&](int cc) {
        const int s   = cc & 1;
        const int seg = cc / segN;
        const int kk  = (cc - seg * segN) << 6;
        const __nv_bfloat16* Ag = PA[seg] + (size_t)bm * K + kk;
        const __nv_bfloat16* Bg = PB[seg] + (size_t)bn * K + kk;
        const uint32_t sa = sbase + s * STAGE_BYTES;
        const uint32_t sb = sa + 128 * SM_STRIDE * 2;
        #pragma unroll
        for (int i = 0; i < 4; i++) {
            const int e = tid + 256 * i;      // 0..1023
            const int r = e >> 3;             // row 0..127
            const int c = e & 7;              // 16B chunk 0..7
            CP_ASYNC16(sa + r * (SM_STRIDE * 2) + c * 16,
                       (const void*)(Ag + (size_t)r * K + c * 8));
            CP_ASYNC16(sb + r * (SM_STRIDE * 2) + c * 16,
                       (const void*)(Bg + (size_t)r * K + c * 8));
        }
        CP_COMMIT();
    };

    float acc[2][8][4];
    #pragma unroll
    for (int mi = 0; mi < 2; mi++)
        #pragma unroll
        for (int ni = 0; ni < 8; ni++)
            #pragma unroll
            for (int q = 0; q < 4; q++) acc[mi][ni][q] = 0.f;

    // ldmatrix lane-address components
    const int a_row_off = (lid & 7) + ((lid >> 3) & 1) * 8;   // row within 16
    const int a_k_off   = ((lid >> 4) & 1) * 8;               // k half
    const int b_n_off   = (lid & 7) + ((lid >> 4) & 1) * 8;   // n within 16
    const int b_k_off   = ((lid >> 3) & 1) * 8;               // k half

    load_chunk(0);

    for (int cc = 0; cc < NCC; cc++) {
        if (cc + 1 < NCC) load_chunk(cc + 1);
        if (cc + 1 < NCC) { CP_WAIT(1); } else { CP_WAIT(0); }
        __syncthreads();

        const int s = cc & 1;
        const uint32_t sa = sbase + s * STAGE_BYTES;
        const uint32_t sb = sa + 128 * SM_STRIDE * 2;

        #pragma unroll
        for (int k16 = 0; k16 < 64; k16 += 16) {
            uint32_t a[2][4];
            #pragma unroll
            for (int mi = 0; mi < 2; mi++) {
                const uint32_t addr = sa +
                    (warp_m * 32 + mi * 16 + a_row_off) * (SM_STRIDE * 2) +
                    (k16 + a_k_off) * 2;
                LDMATRIX_X4(a[mi][0], a[mi][1], a[mi][2], a[mi][3], addr);
            }
            uint32_t b[8][2];
            #pragma unroll
            for (int np = 0; np < 4; np++) {
                const uint32_t addr = sb +
                    (warp_n * 64 + np * 16 + b_n_off) * (SM_STRIDE * 2) +
                    (k16 + b_k_off) * 2;
                uint32_t r0, r1, r2, r3;
                LDMATRIX_X4(r0, r1, r2, r3, addr);
                b[2 * np][0] = r0; b[2 * np][1] = r1;
                b[2 * np + 1][0] = r2; b[2 * np + 1][1] = r3;
            }
            #pragma unroll
            for (int mi = 0; mi < 2; mi++)
                #pragma unroll
                for (int ni = 0; ni < 8; ni++)
                    MMA_BF16(acc[mi][ni][0], acc[mi][ni][1],
                             acc[mi][ni][2], acc[mi][ni][3],
                             a[mi][0], a[mi][1], a[mi][2], a[mi][3],
                             b[ni][0], b[ni][1]);
        }
        __syncthreads();
    }

    // epilogue
    const int lr = lid >> 2;              // 0..7
    const int lc = (lid & 3) * 2;         // 0,2,4,6
    #pragma unroll
    for (int mi = 0; mi < 2; mi++) {
        #pragma unroll
        for (int ni = 0; ni < 8; ni++) {
            const int col = bn + warp_n * 64 + ni * 8 + lc;
            #pragma unroll
            for (int half = 0; half < 2; half++) {
                const int row = bm + warp_m * 32 + mi * 16 + lr + half * 8;
                const size_t off = (size_t)row * N + col;
                float v0 = acc[mi][ni][2 * half];
                float v1 = acc[mi][ni][2 * half + 1];
                if (MODE == 2) {
                    v0 = fmaxf(v0 + bias[col], 0.f);
                    v1 = fmaxf(v1 + bias[col + 1], 0.f);
                    __nv_bfloat16 h0 = bf_hi(v0), h1 = bf_hi(v1);
                    __align__(4) __nv_bfloat16 hp[2] = { h0, h1 };
                    __align__(4) __nv_bfloat16 lp[2] = { bf_lo(v0, h0), bf_lo(v1, h1) };
                    *(uint32_t*)(Oh + off) = *(uint32_t*)hp;
                    *(uint32_t*)(Ol + off) = *(uint32_t*)lp;
                } else {
                    if (MODE == 3) { v0 += bias[col]; v1 += bias[col + 1]; }
                    if (MODE == 1 || MODE == 3) {
                        const float2 rr = *(const float2*)(res + off);
                        v0 += rr.x; v1 += rr.y;
                    }
                    float2 o = make_float2(v0, v1);
                    *(float2*)(Cf + off) = o;
                }
            }
        }
    }
}

// ---------------------------------------------------------------------------
// Causal flash attention (SIMT fp32), output split to bf16 hi/lo
// ---------------------------------------------------------------------------
__global__ void __launch_bounds__(256) attention_kernel(
    const float* __restrict__ Q, const float* __restrict__ K,
    const float* __restrict__ V, __nv_bfloat16* __restrict__ Oh,
    __nv_bfloat16* __restrict__ Ol)
{
    float* smem = (float*)smem_raw;
    float* Qs = smem;            // 64*64
    float* Ks = smem + 4096;     // 64*65 (reused as P)
    float* Vs = smem + 8256;     // 64*64

    const int qt = blockIdx.x;
    const int bh = blockIdx.y;
    const int b  = bh >> 4;
    const int h  = bh & 15;
    const int q0 = qt * 64;
    const size_t base = (size_t)(b * SS) * DMODEL + h * DK;

    const int tid = threadIdx.x;
    const int tr = tid >> 4;
    const int tc = tid & 15;

    for (int i = tid; i < 64 * 16; i += 256) {
        const int r  = i >> 4;
        const int d4 = (i & 15) * 4;
        const float4 qv = *(const float4*)(Q + base + (size_t)(q0 + r) * DMODEL + d4);
        Qs[r * 64 + d4 + 0] = qv.x * 0.125f;
        Qs[r * 64 + d4 + 1] = qv.y * 0.125f;
        Qs[r * 64 + d4 + 2] = qv.z * 0.125f;
        Qs[r * 64 + d4 + 3] = qv.w * 0.125f;
    }

    float m_st[4], l_st[4], o_acc[4][4];
    #pragma unroll
    for (int i = 0; i < 4; i++) {
        m_st[i] = -1e30f; l_st[i] = 0.f;
        #pragma unroll
        for (int j = 0; j < 4; j++) o_acc[i][j] = 0.f;
    }

    for (int kt = 0; kt <= qt; kt++) {
        __syncthreads();
        for (int i = tid; i < 64 * 16; i += 256) {
            const int r  = i >> 4;
            const int d4 = (i & 15) * 4;
            const float4 kv = *(const float4*)(K + base + (size_t)(kt * 64 + r) * DMODEL + d4);
            Ks[r * 65 + d4 + 0] = kv.x;
            Ks[r * 65 + d4 + 1] = kv.y;
            Ks[r * 65 + d4 + 2] = kv.z;
            Ks[r * 65 + d4 + 3] = kv.w;
            const float4 vv = *(const float4*)(V + base + (size_t)(kt * 64 + r) * DMODEL + d4);
            *(float4*)&Vs[r * 64 + d4] = vv;
        }
        __syncthreads();

        float s[4][4];
        #pragma unroll
        for (int i = 0; i < 4; i++)
            #pragma unroll
            for (int j = 0; j < 4; j++) s[i][j] = 0.f;

        #pragma unroll 16
        for (int d = 0; d < 64; d++) {
            float qv[4], kv[4];
            #pragma unroll
            for (int i = 0; i < 4; i++) qv[i] = Qs[(4 * tr + i) * 64 + d];
            #pragma unroll
            for (int j = 0; j < 4; j++) kv[j] = Ks[(4 * tc + j) * 65 + d];
            #pragma unroll
            for (int i = 0; i < 4; i++)
                #pragma unroll
                for (int j = 0; j < 4; j++)
                    s[i][j] = fmaf(qv[i], kv[j], s[i][j]);
        }

        if (kt == qt) {
            #pragma unroll
            for (int i = 0; i < 4; i++)
                #pragma unroll
                for (int j = 0; j < 4; j++)
                    if (4 * tc + j > 4 * tr + i) s[i][j] = -1e30f;
        }

        #pragma unroll
        for (int i = 0; i < 4; i++) {
            float mt = fmaxf(fmaxf(s[i][0], s[i][1]), fmaxf(s[i][2], s[i][3]));
            #pragma unroll
            for (int off = 8; off > 0; off >>= 1)
                mt = fmaxf(mt, __shfl_xor_sync(0xffffffffu, mt, off));
            const float mnew = fmaxf(m_st[i], mt);
            float rs = 0.f;
            #pragma unroll
            for (int j = 0; j < 4; j++) { s[i][j] = __expf(s[i][j] - mnew); rs += s[i][j]; }
            #pragma unroll
            for (int off = 8; off > 0; off >>= 1)
                rs += __shfl_xor_sync(0xffffffffu, rs, off);
            const float corr = __expf(m_st[i] - mnew);
            m_st[i] = mnew;
            l_st[i] = l_st[i] * corr + rs;
            #pragma unroll
            for (int j = 0; j < 4; j++) o_acc[i][j] *= corr;
        }

        __syncthreads();
        #pragma unroll
        for (int i = 0; i < 4; i++)
            #pragma unroll
            for (int j = 0; j < 4; j++)
                Ks[(4 * tr + i) * 65 + 4 * tc + j] = s[i][j];
        __syncthreads();

        #pragma unroll 16
        for (int cidx = 0; cidx < 64; cidx++) {
            float pv[4], vv[4];
            #pragma unroll
            for (int i = 0; i < 4; i++) pv[i] = Ks[(4 * tr + i) * 65 + cidx];
            #pragma unroll
            for (int j = 0; j < 4; j++) vv[j] = Vs[cidx * 64 + 4 * tc + j];
            #pragma unroll
            for (int i = 0; i < 4; i++)
                #pragma unroll
                for (int j = 0; j < 4; j++)
                    o_acc[i][j] = fmaf(pv[i], vv[j], o_acc[i][j]);
        }
    }

    #pragma unroll
    for (int i = 0; i < 4; i++) {
        const float inv = 1.f / l_st[i];
        __align__(8) __nv_bfloat16 h4[4], l4[4];
        #pragma unroll
        for (int j = 0; j < 4; j++) {
            const float v = o_acc[i][j] * inv;
            h4[j] = bf_hi(v);
            l4[j] = bf_lo(v, h4[j]);
        }
        const size_t idx = base + (size_t)(q0 + 4 * tr + i) * DMODEL + 4 * tc;
        *(uint2*)(Oh + idx) = *(uint2*)h4;
        *(uint2*)(Ol + idx) = *(uint2*)l4;
    }
}

// ---------------------------------------------------------------------------
// Launch
// ---------------------------------------------------------------------------
extern "C" void kernel_launch(void* const* d_in, const int* in_sizes, int n_in,
                              void* d_out, int out_size)
{
    const float* x   = (const float*)d_in[0];
    const float* Wq  = (const float*)d_in[1];
    const float* Wk  = (const float*)d_in[2];
    const float* Wv  = (const float*)d_in[3];
    const float* Wo  = (const float*)d_in[4];
    const float* W1  = (const float*)d_in[5];
    const float* b1  = (const float*)d_in[6];
    const float* W2  = (const float*)d_in[7];
    const float* b2  = (const float*)d_in[8];
    const float* g1  = (const float*)d_in[9];
    const float* be1 = (const float*)d_in[10];
    const float* g2  = (const float*)d_in[11];
    const float* be2 = (const float*)d_in[12];
    float* out = (float*)d_out;

    float *q, *k, *v, *x2;
    __nv_bfloat16 *ah, *al, *fh, *fl, *wh, *wl;
    cudaGetSymbolAddress((void**)&q,  g_q);
    cudaGetSymbolAddress((void**)&k,  g_k);
    cudaGetSymbolAddress((void**)&v,  g_v);
    cudaGetSymbolAddress((void**)&x2, g_x2);
    cudaGetSymbolAddress((void**)&ah, g_a_hi);
    cudaGetSymbolAddress((void**)&al, g_a_lo);
    cudaGetSymbolAddress((void**)&fh, g_f_hi);
    cudaGetSymbolAddress((void**)&fl, g_f_lo);
    cudaGetSymbolAddress((void**)&wh, g_w_hi);
    cudaGetSymbolAddress((void**)&wl, g_w_lo);

    const int GEMM_SMEM = 2 * STAGE_BYTES;   // 73728
    cudaFuncSetAttribute(gemm_mma_kernel<0>, cudaFuncAttributeMaxDynamicSharedMemorySize, GEMM_SMEM);
    cudaFuncSetAttribute(gemm_mma_kernel<1>, cudaFuncAttributeMaxDynamicSharedMemorySize, GEMM_SMEM);
    cudaFuncSetAttribute(gemm_mma_kernel<2>, cudaFuncAttributeMaxDynamicSharedMemorySize, GEMM_SMEM);
    cudaFuncSetAttribute(gemm_mma_kernel<3>, cudaFuncAttributeMaxDynamicSharedMemorySize, GEMM_SMEM);
    const int ATTN_SMEM = (64 * 64 + 64 * 65 + 64 * 64) * (int)sizeof(float);
    cudaFuncSetAttribute(attention_kernel, cudaFuncAttributeMaxDynamicSharedMemorySize, ATTN_SMEM);

    // 0) weight transpose + bf16 split
    {
        dim3 tb(32, 8);
        transpose_split_kernel<<<dim3(32,  32), tb>>>(Wq, wh + 0 * MEG, wl + 0 * MEG, 1024, 1024);
        transpose_split_kernel<<<dim3(32,  32), tb>>>(Wk, wh + 1 * MEG, wl + 1 * MEG, 1024, 1024);
        transpose_split_kernel<<<dim3(32,  32), tb>>>(Wv, wh + 2 * MEG, wl + 2 * MEG, 1024, 1024);
        transpose_split_kernel<<<dim3(32,  32), tb>>>(Wo, wh + 3 * MEG, wl + 3 * MEG, 1024, 1024);
        transpose_split_kernel<<<dim3(128, 32), tb>>>(W1, wh + 4 * MEG, wl + 4 * MEG, 1024, 4096);
        transpose_split_kernel<<<dim3(32, 128), tb>>>(W2, wh + 8 * MEG, wl + 8 * MEG, 4096, 1024);
    }

    // 1) LN1 -> bf16 split
    layernorm_split_kernel<<<MROWS, 256>>>(x, g1, be1, ah, al);

    // 2-4) Q, K, V projections
    {
        dim3 grid(DMODEL / 128, MROWS / 128);
        gemm_mma_kernel<0><<<grid, 256, GEMM_SMEM>>>(ah, al, wh + 0 * MEG, wl + 0 * MEG,
            nullptr, nullptr, q, nullptr, nullptr, MROWS, DMODEL, DMODEL);
        gemm_mma_kernel<0><<<grid, 256, GEMM_SMEM>>>(ah, al, wh + 1 * MEG, wl + 1 * MEG,
            nullptr, nullptr, k, nullptr, nullptr, MROWS, DMODEL, DMODEL);
        gemm_mma_kernel<0><<<grid, 256, GEMM_SMEM>>>(ah, al, wh + 2 * MEG, wl + 2 * MEG,
            nullptr, nullptr, v, nullptr, nullptr, MROWS, DMODEL, DMODEL);
    }

    // 5) causal attention -> att (bf16 split, reuses ah/al)
    {
        dim3 grid(SS / 64, BB * NHEADS);
        attention_kernel<<<grid, 256, ATTN_SMEM>>>(q, k, v, ah, al);
    }

    // 6) output projection + residual(x) -> x2 (f32)
    {
        dim3 grid(DMODEL / 128, MROWS / 128);
        gemm_mma_kernel<1><<<grid, 256, GEMM_SMEM>>>(ah, al, wh + 3 * MEG, wl + 3 * MEG,
            nullptr, x, x2, nullptr, nullptr, MROWS, DMODEL, DMODEL);
    }

    // 7) LN2 -> bf16 split (reuses ah/al)
    layernorm_split_kernel<<<MROWS, 256>>>(x2, g2, be2, ah, al);

    // 8) FFN1: relu(h2 @ W1 + b1) -> bf16 split (fh/fl)
    {
        dim3 grid(DFF / 128, MROWS / 128);
        gemm_mma_kernel<2><<<grid, 256, GEMM_SMEM>>>(ah, al, wh + 4 * MEG, wl + 4 * MEG,
            b1, nullptr, nullptr, fh, fl, MROWS, DFF, DMODEL);
    }

    // 9) FFN2: ff @ W2 + b2 + x2 -> out (f32)
    {
        dim3 grid(DMODEL / 128, MROWS / 128);
        gemm_mma_kernel<3><<<grid, 256, GEMM_SMEM>>>(fh, fl, wh + 8 * MEG, wl + 8 * MEG,
            b2, x2, out, nullptr, nullptr, MROWS, DMODEL, DFF);
    }
}

// round 5
// speedup vs baseline: 2.3905x; 1.1036x over previous
#include <cuda_runtime.h>
#include <cuda_bf16.h>
#include <cstdint>
#include <math.h>

// ---------------------------------------------------------------------------
// Problem dims
// ---------------------------------------------------------------------------
#define BB      16
#define SS      512
#define DMODEL  1024
#define NHEADS  16
#define DK      64
#define DFF     4096
#define MROWS   (BB * SS)          // 8192
#define MEG     (1024 * 1024)
#define QKVN    3072

// ---------------------------------------------------------------------------
// Scratch (device globals)
// ---------------------------------------------------------------------------
__device__ float g_x2 [MROWS * DMODEL];
__device__ __nv_bfloat16 g_a_hi[MROWS * DMODEL];   // activations (ln1 / att / ln2)
__device__ __nv_bfloat16 g_a_lo[MROWS * DMODEL];
__device__ __nv_bfloat16 g_qkv_hi[MROWS * QKVN];   // fused q|k|v
__device__ __nv_bfloat16 g_qkv_lo[MROWS * QKVN];
__device__ __nv_bfloat16 g_f_hi[MROWS * DFF];      // ffn intermediate
__device__ __nv_bfloat16 g_f_lo[MROWS * DFF];
__device__ __nv_bfloat16 g_w_hi[12 * MEG];         // transposed weights (hi)
__device__ __nv_bfloat16 g_w_lo[12 * MEG];         // transposed weights (lo)
// offsets: Wq=0, Wk=1M, Wv=2M (contiguous [3072][1024]), Wo=3M, W1t=4M, W2t=8M

extern __shared__ char smem_raw[];

// ---------------------------------------------------------------------------
// PTX helpers (baseline features only)
// ---------------------------------------------------------------------------
__device__ __forceinline__ uint32_t smem_u32(const void* p) {
    uint32_t a;
    asm("{ .reg .u64 t; cvta.to.shared.u64 t, %1; cvt.u32.u64 %0, t; }"
        : "=r"(a) : "l"(p));
    return a;
}
#define CP_ASYNC16(dst, src) \
    asm volatile("cp.async.cg.shared.global [%0], [%1], 16;" :: "r"(dst), "l"(src))
#define CP_COMMIT() asm volatile("cp.async.commit_group;" ::: "memory")
#define CP_WAIT(n)  asm volatile("cp.async.wait_group %0;" :: "n"(n) : "memory")

#define LDMATRIX_X4(r0, r1, r2, r3, addr) \
    asm volatile("ldmatrix.sync.aligned.m8n8.x4.shared.b16 {%0,%1,%2,%3}, [%4];" \
                 : "=r"(r0), "=r"(r1), "=r"(r2), "=r"(r3) : "r"(addr))
#define LDMATRIX_X4_T(r0, r1, r2, r3, addr) \
    asm volatile("ldmatrix.sync.aligned.m8n8.x4.trans.shared.b16 {%0,%1,%2,%3}, [%4];" \
                 : "=r"(r0), "=r"(r1), "=r"(r2), "=r"(r3) : "r"(addr))

#define MMA_BF16(c0, c1, c2, c3, a0, a1, a2, a3, b0, b1) \
    asm volatile("mma.sync.aligned.m16n8k16.row.col.f32.bf16.bf16.f32 " \
                 "{%0,%1,%2,%3}, {%4,%5,%6,%7}, {%8,%9}, {%0,%1,%2,%3};" \
                 : "+f"(c0), "+f"(c1), "+f"(c2), "+f"(c3) \
                 : "r"(a0), "r"(a1), "r"(a2), "r"(a3), "r"(b0), "r"(b1))

__device__ __forceinline__ __nv_bfloat16 bf_hi(float v) { return __float2bfloat16(v); }
__device__ __forceinline__ __nv_bfloat16 bf_lo(float v, __nv_bfloat16 h) {
    return __float2bfloat16(v - __bfloat162float(h));
}
__device__ __forceinline__ uint32_t pack2(__nv_bfloat16 x, __nv_bfloat16 y) {
    return (uint32_t)__bfloat16_as_ushort(x) |
           ((uint32_t)__bfloat16_as_ushort(y) << 16);
}

// ---------------------------------------------------------------------------
// Weight transpose + bf16 split
// ---------------------------------------------------------------------------
__global__ void __launch_bounds__(256) transpose_split_kernel(
    const float* __restrict__ W, __nv_bfloat16* __restrict__ oh,
    __nv_bfloat16* __restrict__ ol, int K, int N)
{
    __shared__ float t[32][33];
    const int tx = threadIdx.x, ty = threadIdx.y;
    const int n0 = blockIdx.x * 32;
    const int k0 = blockIdx.y * 32;
    #pragma unroll
    for (int j = 0; j < 32; j += 8)
        t[ty + j][tx] = W[(size_t)(k0 + ty + j) * N + n0 + tx];
    __syncthreads();
    #pragma unroll
    for (int j = 0; j < 32; j += 8) {
        const float v = t[tx][ty + j];
        const __nv_bfloat16 h = bf_hi(v);
        const size_t idx = (size_t)(n0 + ty + j) * K + k0 + tx;
        oh[idx] = h;
        ol[idx] = bf_lo(v, h);
    }
}

// ---------------------------------------------------------------------------
// LayerNorm -> bf16 hi/lo split
// ---------------------------------------------------------------------------
__global__ void __launch_bounds__(256) layernorm_split_kernel(
    const float* __restrict__ x, const float* __restrict__ g,
    const float* __restrict__ be, __nv_bfloat16* __restrict__ oh,
    __nv_bfloat16* __restrict__ ol)
{
    const int row = blockIdx.x;
    const int tid = threadIdx.x;
    const float4 v = *(const float4*)(x + (size_t)row * DMODEL + tid * 4);

    float s1 = v.x + v.y + v.z + v.w;
    float s2 = v.x * v.x + v.y * v.y + v.z * v.z + v.w * v.w;
    #pragma unroll
    for (int off = 16; off > 0; off >>= 1) {
        s1 += __shfl_xor_sync(0xffffffffu, s1, off);
        s2 += __shfl_xor_sync(0xffffffffu, s2, off);
    }
    __shared__ float sm1[8], sm2[8];
    const int w = tid >> 5, l = tid & 31;
    if (l == 0) { sm1[w] = s1; sm2[w] = s2; }
    __syncthreads();
    if (w == 0) {
        s1 = (l < 8) ? sm1[l] : 0.f;
        s2 = (l < 8) ? sm2[l] : 0.f;
        #pragma unroll
        for (int off = 4; off > 0; off >>= 1) {
            s1 += __shfl_xor_sync(0xffffffffu, s1, off);
            s2 += __shfl_xor_sync(0xffffffffu, s2, off);
        }
        if (l == 0) { sm1[0] = s1; sm2[0] = s2; }
    }
    __syncthreads();

    const float mu  = sm1[0] * (1.f / DMODEL);
    const float var = sm2[0] * (1.f / DMODEL) - mu * mu;
    const float inv = rsqrtf(var + 1e-5f);

    const float4 gv = *(const float4*)(g  + tid * 4);
    const float4 bv = *(const float4*)(be + tid * 4);
    float o[4];
    o[0] = (v.x - mu) * inv * gv.x + bv.x;
    o[1] = (v.y - mu) * inv * gv.y + bv.y;
    o[2] = (v.z - mu) * inv * gv.z + bv.z;
    o[3] = (v.w - mu) * inv * gv.w + bv.w;

    __align__(8) __nv_bfloat16 h4[4], l4[4];
    #pragma unroll
    for (int j = 0; j < 4; j++) { h4[j] = bf_hi(o[j]); l4[j] = bf_lo(o[j], h4[j]); }
    const size_t idx = (size_t)row * DMODEL + tid * 4;
    *(uint2*)(oh + idx) = *(uint2*)h4;
    *(uint2*)(ol + idx) = *(uint2*)l4;
}

// ---------------------------------------------------------------------------
// mma.sync bf16 split-3 GEMM (as round 4)
// MODE: 1 = f32 +res | 2 = bf16 hi/lo relu(+bias) | 3 = f32 +bias +res | 4 = bf16 hi/lo plain
// ---------------------------------------------------------------------------
#define SM_STRIDE 72
#define STAGE_BYTES (128 * SM_STRIDE * 2 * 2)

template<int MODE>
__global__ void __launch_bounds__(256, 2) gemm_mma_kernel(
    const __nv_bfloat16* __restrict__ Ah, const __nv_bfloat16* __restrict__ Al,
    const __nv_bfloat16* __restrict__ Bh, const __nv_bfloat16* __restrict__ Bl,
    const float* __restrict__ bias, const float* __restrict__ res,
    float* __restrict__ Cf, __nv_bfloat16* __restrict__ Oh,
    __nv_bfloat16* __restrict__ Ol, int M, int N, int K)
{
    const uint32_t sbase = smem_u32(smem_raw);
    const int tid = threadIdx.x;
    const int wid = tid >> 5, lid = tid & 31;
    const int warp_m = wid & 3;
    const int warp_n = wid >> 2;
    const int bm = blockIdx.y * 128;
    const int bn = blockIdx.x * 128;

    const __nv_bfloat16* PA[3] = { Ah, Ah, Al };
    const __nv_bfloat16* PB[3] = { Bh, Bl, Bh };

    const int segN = K >> 6;
    const int NCC  = 3 * segN;

    auto load_chunk = [&](int cc) {
        const int s   = cc & 1;
        const int seg = cc / segN;
        const int kk  = (cc - seg * segN) << 6;
        const __nv_bfloat16* Ag = PA[seg] + (size_t)bm * K + kk;
        const __nv_bfloat16* Bg = PB[seg] + (size_t)bn * K + kk;
        const uint32_t sa = sbase + s * STAGE_BYTES;
        const uint32_t sb = sa + 128 * SM_STRIDE * 2;
        #pragma unroll
        for (int i = 0; i < 4; i++) {
            const int e = tid + 256 * i;
            const int r = e >> 3;
            const int c = e & 7;
            CP_ASYNC16(sa + r * (SM_STRIDE * 2) + c * 16,
                       (const void*)(Ag + (size_t)r * K + c * 8));
            CP_ASYNC16(sb + r * (SM_STRIDE * 2) + c * 16,
                       (const void*)(Bg + (size_t)r * K + c * 8));
        }
        CP_COMMIT();
    };

    float acc[2][8][4];
    #pragma unroll
    for (int mi = 0; mi < 2; mi++)
        #pragma unroll
        for (int ni = 0; ni < 8; ni++)
            #pragma unroll
            for (int q = 0; q < 4; q++) acc[mi][ni][q] = 0.f;

    const int a_row_off = (lid & 7) + ((lid >> 3) & 1) * 8;
    const int a_k_off   = ((lid >> 4) & 1) * 8;
    const int b_n_off   = (lid & 7) + ((lid >> 4) & 1) * 8;
    const int b_k_off   = ((lid >> 3) & 1) * 8;

    load_chunk(0);

    for (int cc = 0; cc < NCC; cc++) {
        if (cc + 1 < NCC) load_chunk(cc + 1);
        if (cc + 1 < NCC) { CP_WAIT(1); } else { CP_WAIT(0); }
        __syncthreads();

        const int s = cc & 1;
        const uint32_t sa = sbase + s * STAGE_BYTES;
        const uint32_t sb = sa + 128 * SM_STRIDE * 2;

        #pragma unroll
        for (int k16 = 0; k16 < 64; k16 += 16) {
            uint32_t a[2][4];
            #pragma unroll
            for (int mi = 0; mi < 2; mi++) {
                const uint32_t addr = sa +
                    (warp_m * 32 + mi * 16 + a_row_off) * (SM_STRIDE * 2) +
                    (k16 + a_k_off) * 2;
                LDMATRIX_X4(a[mi][0], a[mi][1], a[mi][2], a[mi][3], addr);
            }
            uint32_t b[8][2];
            #pragma unroll
            for (int np = 0; np < 4; np++) {
                const uint32_t addr = sb +
                    (warp_n * 64 + np * 16 + b_n_off) * (SM_STRIDE * 2) +
                    (k16 + b_k_off) * 2;
                uint32_t r0, r1, r2, r3;
                LDMATRIX_X4(r0, r1, r2, r3, addr);
                b[2 * np][0] = r0; b[2 * np][1] = r1;
                b[2 * np + 1][0] = r2; b[2 * np + 1][1] = r3;
            }
            #pragma unroll
            for (int mi = 0; mi < 2; mi++)
                #pragma unroll
                for (int ni = 0; ni < 8; ni++)
                    MMA_BF16(acc[mi][ni][0], acc[mi][ni][1],
                             acc[mi][ni][2], acc[mi][ni][3],
                             a[mi][0], a[mi][1], a[mi][2], a[mi][3],
                             b[ni][0], b[ni][1]);
        }
        __syncthreads();
    }

    const int lr = lid >> 2;
    const int lc = (lid & 3) * 2;
    #pragma unroll
    for (int mi = 0; mi < 2; mi++) {
        #pragma unroll
        for (int ni = 0; ni < 8; ni++) {
            const int col = bn + warp_n * 64 + ni * 8 + lc;
            #pragma unroll
            for (int half = 0; half < 2; half++) {
                const int row = bm + warp_m * 32 + mi * 16 + lr + half * 8;
                const size_t off = (size_t)row * N + col;
                float v0 = acc[mi][ni][2 * half];
                float v1 = acc[mi][ni][2 * half + 1];
                if (MODE == 2 || MODE == 4) {
                    if (MODE == 2) {
                        v0 = fmaxf(v0 + bias[col], 0.f);
                        v1 = fmaxf(v1 + bias[col + 1], 0.f);
                    }
                    __nv_bfloat16 h0 = bf_hi(v0), h1 = bf_hi(v1);
                    *(uint32_t*)(Oh + off) = pack2(h0, h1);
                    *(uint32_t*)(Ol + off) = pack2(bf_lo(v0, h0), bf_lo(v1, h1));
                } else {
                    if (MODE == 3) { v0 += bias[col]; v1 += bias[col + 1]; }
                    const float2 rr = *(const float2*)(res + off);
                    v0 += rr.x; v1 += rr.y;
                    *(float2*)(Cf + off) = make_float2(v0, v1);
                }
            }
        }
    }
}

// ---------------------------------------------------------------------------
// Tensor-core causal flash attention, split-3 bf16.
// QKV layout: [row][3072] hi/lo, Q at h*64, K at 1024+h*64, V at 2048+h*64.
// Block: 128 threads (4 warps). 64 q-rows per block; warp w owns rows 16w..16w+15.
// smem: Qh Ql Kh Kl Vh Vl, each [64][72] bf16 (stride 144B).
// ---------------------------------------------------------------------------
#define ATT_STR  72
#define ATT_STRB (ATT_STR * 2)
#define ATT_TILE (64 * ATT_STR)            // bf16 elems per tile

__global__ void __launch_bounds__(128) attention_mma_kernel(
    const __nv_bfloat16* __restrict__ QKVh, const __nv_bfloat16* __restrict__ QKVl,
    __nv_bfloat16* __restrict__ Oh, __nv_bfloat16* __restrict__ Ol)
{
    const uint32_t sbase = smem_u32(smem_raw);
    const uint32_t sQh = sbase;
    const uint32_t sQl = sQh + ATT_TILE * 2;
    const uint32_t sKh = sQl + ATT_TILE * 2;
    const uint32_t sKl = sKh + ATT_TILE * 2;
    const uint32_t sVh = sKl + ATT_TILE * 2;
    const uint32_t sVl = sVh + ATT_TILE * 2;

    const int qt = blockIdx.x;
    const int bh = blockIdx.y;
    const int b  = bh >> 4;
    const int h  = bh & 15;
    const int q0 = qt * 64;
    const size_t rowbase = (size_t)b * SS;

    const int tid = threadIdx.x;
    const int w   = tid >> 5;
    const int lid = tid & 31;
    const int lr  = lid >> 2;
    const int lq  = lid & 3;

    // ldmatrix lane offsets (same pattern as GEMM)
    const int a_row_off = (lid & 7) + ((lid >> 3) & 1) * 8;
    const int a_k_off   = ((lid >> 4) & 1) * 8;
    const int b_n_off   = (lid & 7) + ((lid >> 4) & 1) * 8;
    const int b_k_off   = ((lid >> 3) & 1) * 8;
    // trans ldmatrix (V stored [kpos][d])
    const int v_row_off = (lid & 7) + ((lid >> 3) & 1) * 8;
    const int v_col_off = ((lid >> 4) & 1) * 8;

    // ---- load Q tiles (hi/lo), scaled by 0.125 (exact) ----
    {
        const size_t qcol = (size_t)h * DK;
        #pragma unroll
        for (int i = 0; i < 4; i++) {
            const int e = tid + 128 * i;       // 0..511
            const int r = e >> 3;
            const int c = e & 7;
            const size_t g = (rowbase + q0 + r) * QKVN + qcol + c * 8;
            const uint32_t sm = r * ATT_STRB + c * 16;
            uint4 vh = *(const uint4*)(QKVh + g);
            uint4 vl = *(const uint4*)(QKVl + g);
            __nv_bfloat16* ph = (__nv_bfloat16*)&vh;
            __nv_bfloat16* pl = (__nv_bfloat16*)&vl;
            #pragma unroll
            for (int j = 0; j < 8; j++) {
                ph[j] = __float2bfloat16(__bfloat162float(ph[j]) * 0.125f);
                pl[j] = __float2bfloat16(__bfloat162float(pl[j]) * 0.125f);
            }
            *(uint4*)(smem_raw + (sQh - sbase) + sm) = vh;
            *(uint4*)(smem_raw + (sQl - sbase) + sm) = vl;
        }
    }

    float m0 = -1e30f, m1 = -1e30f, l0 = 0.f, l1 = 0.f;
    float o[8][4];
    #pragma unroll
    for (int ni = 0; ni < 8; ni++)
        #pragma unroll
        for (int q = 0; q < 4; q++) o[ni][q] = 0.f;

    for (int kt = 0; kt <= qt; kt++) {
        __syncthreads();     // previous-iter reads of K/V smem done; Q ready (1st iter)
        // ---- load K,V tiles via cp.async ----
        {
            const size_t kcol = 1024 + (size_t)h * DK;
            const size_t vcol = 2048 + (size_t)h * DK;
            #pragma unroll
            for (int i = 0; i < 4; i++) {
                const int e = tid + 128 * i;   // 0..511
                const int r = e >> 3;
                const int c = e & 7;
                const size_t grow = (rowbase + kt * 64 + r) * QKVN;
                const uint32_t sm = r * ATT_STRB + c * 16;
                CP_ASYNC16(sKh + sm, (const void*)(QKVh + grow + kcol + c * 8));
                CP_ASYNC16(sKl + sm, (const void*)(QKVl + grow + kcol + c * 8));
                CP_ASYNC16(sVh + sm, (const void*)(QKVh + grow + vcol + c * 8));
                CP_ASYNC16(sVl + sm, (const void*)(QKVl + grow + vcol + c * 8));
            }
        }
        CP_COMMIT();
        CP_WAIT(0);
        __syncthreads();

        // ---- S = Q K^T (split-3) ----
        float s[8][4];
        #pragma unroll
        for (int ni = 0; ni < 8; ni++)
            #pragma unroll
            for (int q = 0; q < 4; q++) s[ni][q] = 0.f;

        const uint32_t QT[3] = { sQh, sQh, sQl };
        const uint32_t KT[3] = { sKh, sKl, sKh };
        #pragma unroll
        for (int p = 0; p < 3; p++) {
            #pragma unroll
            for (int k16 = 0; k16 < 64; k16 += 16) {
                uint32_t a0, a1, a2, a3;
                LDMATRIX_X4(a0, a1, a2, a3,
                    QT[p] + (w * 16 + a_row_off) * ATT_STRB + (k16 + a_k_off) * 2);
                uint32_t bb[8][2];
                #pragma unroll
                for (int np = 0; np < 4; np++) {
                    uint32_t r0, r1, r2, r3;
                    LDMATRIX_X4(r0, r1, r2, r3,
                        KT[p] + (np * 16 + b_n_off) * ATT_STRB + (k16 + b_k_off) * 2);
                    bb[2 * np][0] = r0; bb[2 * np][1] = r1;
                    bb[2 * np + 1][0] = r2; bb[2 * np + 1][1] = r3;
                }
                #pragma unroll
                for (int ni = 0; ni < 8; ni++)
                    MMA_BF16(s[ni][0], s[ni][1], s[ni][2], s[ni][3],
                             a0, a1, a2, a3, bb[ni][0], bb[ni][1]);
            }
        }

        // ---- causal mask on diagonal tile ----
        if (kt == qt) {
            const int r0l = w * 16 + lr;
            const int r1l = r0l + 8;
            #pragma unroll
            for (int ni = 0; ni < 8; ni++) {
                const int c0 = ni * 8 + lq * 2;
                if (c0 > r0l)     s[ni][0] = -1e30f;
                if (c0 + 1 > r0l) s[ni][1] = -1e30f;
                if (c0 > r1l)     s[ni][2] = -1e30f;
                if (c0 + 1 > r1l) s[ni][3] = -1e30f;
            }
        }

        // ---- online softmax (rows lr, lr+8; quad reduce over lanes lq) ----
        float mt0 = -1e30f, mt1 = -1e30f;
        #pragma unroll
        for (int ni = 0; ni < 8; ni++) {
            mt0 = fmaxf(mt0, fmaxf(s[ni][0], s[ni][1]));
            mt1 = fmaxf(mt1, fmaxf(s[ni][2], s[ni][3]));
        }
        mt0 = fmaxf(mt0, __shfl_xor_sync(0xffffffffu, mt0, 1));
        mt0 = fmaxf(mt0, __shfl_xor_sync(0xffffffffu, mt0, 2));
        mt1 = fmaxf(mt1, __shfl_xor_sync(0xffffffffu, mt1, 1));
        mt1 = fmaxf(mt1, __shfl_xor_sync(0xffffffffu, mt1, 2));
        const float mn0 = fmaxf(m0, mt0), mn1 = fmaxf(m1, mt1);
        const float cr0 = __expf(m0 - mn0), cr1 = __expf(m1 - mn1);
        float rs0 = 0.f, rs1 = 0.f;
        #pragma unroll
        for (int ni = 0; ni < 8; ni++) {
            s[ni][0] = __expf(s[ni][0] - mn0); rs0 += s[ni][0];
            s[ni][1] = __expf(s[ni][1] - mn0); rs0 += s[ni][1];
            s[ni][2] = __expf(s[ni][2] - mn1); rs1 += s[ni][2];
            s[ni][3] = __expf(s[ni][3] - mn1); rs1 += s[ni][3];
        }
        rs0 += __shfl_xor_sync(0xffffffffu, rs0, 1);
        rs0 += __shfl_xor_sync(0xffffffffu, rs0, 2);
        rs1 += __shfl_xor_sync(0xffffffffu, rs1, 1);
        rs1 += __shfl_xor_sync(0xffffffffu, rs1, 2);
        l0 = l0 * cr0 + rs0;  l1 = l1 * cr1 + rs1;
        m0 = mn0;  m1 = mn1;
        #pragma unroll
        for (int ni = 0; ni < 8; ni++) {
            o[ni][0] *= cr0; o[ni][1] *= cr0;
            o[ni][2] *= cr1; o[ni][3] *= cr1;
        }

        // ---- O += P V (split-3; P frags built from s registers) ----
        #pragma unroll
        for (int j = 0; j < 4; j++) {          // k16 = 16j over kpos
            const int t0 = 2 * j, t1 = 2 * j + 1;
            __nv_bfloat16 h00 = bf_hi(s[t0][0]), h01 = bf_hi(s[t0][1]);
            __nv_bfloat16 h02 = bf_hi(s[t0][2]), h03 = bf_hi(s[t0][3]);
            __nv_bfloat16 h10 = bf_hi(s[t1][0]), h11 = bf_hi(s[t1][1]);
            __nv_bfloat16 h12 = bf_hi(s[t1][2]), h13 = bf_hi(s[t1][3]);
            const uint32_t ah0 = pack2(h00, h01);
            const uint32_t ah1 = pack2(h02, h03);
            const uint32_t ah2 = pack2(h10, h11);
            const uint32_t ah3 = pack2(h12, h13);
            const uint32_t al0 = pack2(bf_lo(s[t0][0], h00), bf_lo(s[t0][1], h01));
            const uint32_t al1 = pack2(bf_lo(s[t0][2], h02), bf_lo(s[t0][3], h03));
            const uint32_t al2 = pack2(bf_lo(s[t1][0], h10), bf_lo(s[t1][1], h11));
            const uint32_t al3 = pack2(bf_lo(s[t1][2], h12), bf_lo(s[t1][3], h13));

            #pragma unroll
            for (int np = 0; np < 4; np++) {   // d n-pairs (16 cols)
                uint32_t bh0, bh1, bh2, bh3, bl0, bl1, bl2, bl3;
                const uint32_t vaddr =
                    (j * 16 + v_row_off) * ATT_STRB + (np * 16 + v_col_off) * 2;
                LDMATRIX_X4_T(bh0, bh1, bh2, bh3, sVh + vaddr);
                LDMATRIX_X4_T(bl0, bl1, bl2, bl3, sVl + vaddr);
                // Ph*Vh
                MMA_BF16(o[2*np][0], o[2*np][1], o[2*np][2], o[2*np][3],
                         ah0, ah1, ah2, ah3, bh0, bh1);
                MMA_BF16(o[2*np+1][0], o[2*np+1][1], o[2*np+1][2], o[2*np+1][3],
                         ah0, ah1, ah2, ah3, bh2, bh3);
                // Ph*Vl
                MMA_BF16(o[2*np][0], o[2*np][1], o[2*np][2], o[2*np][3],
                         ah0, ah1, ah2, ah3, bl0, bl1);
                MMA_BF16(o[2*np+1][0], o[2*np+1][1], o[2*np+1][2], o[2*np+1][3],
                         ah0, ah1, ah2, ah3, bl2, bl3);
                // Pl*Vh
                MMA_BF16(o[2*np][0], o[2*np][1], o[2*np][2], o[2*np][3],
                         al0, al1, al2, al3, bh0, bh1);
                MMA_BF16(o[2*np+1][0], o[2*np+1][1], o[2*np+1][2], o[2*np+1][3],
                         al0, al1, al2, al3, bh2, bh3);
            }
        }
    }

    // ---- finalize: O /= l, split to bf16 hi/lo, write [row][h*64+d] ----
    const float inv0 = 1.f / l0, inv1 = 1.f / l1;
    #pragma unroll
    for (int ni = 0; ni < 8; ni++) {
        const int col = h * DK + ni * 8 + lq * 2;
        {
            const size_t off = (rowbase + q0 + w * 16 + lr) * DMODEL + col;
            const float f0 = o[ni][0] * inv0, f1 = o[ni][1] * inv0;
            __nv_bfloat16 h0 = bf_hi(f0), h1 = bf_hi(f1);
            *(uint32_t*)(Oh + off) = pack2(h0, h1);
            *(uint32_t*)(Ol + off) = pack2(bf_lo(f0, h0), bf_lo(f1, h1));
        }
        {
            const size_t off = (rowbase + q0 + w * 16 + lr + 8) * DMODEL + col;
            const float f0 = o[ni][2] * inv1, f1 = o[ni][3] * inv1;
            __nv_bfloat16 h0 = bf_hi(f0), h1 = bf_hi(f1);
            *(uint32_t*)(Oh + off) = pack2(h0, h1);
            *(uint32_t*)(Ol + off) = pack2(bf_lo(f0, h0), bf_lo(f1, h1));
        }
    }
}

// ---------------------------------------------------------------------------
// Launch
// ---------------------------------------------------------------------------
extern "C" void kernel_launch(void* const* d_in, const int* in_sizes, int n_in,
                              void* d_out, int out_size)
{
    const float* x   = (const float*)d_in[0];
    const float* Wq  = (const float*)d_in[1];
    const float* Wk  = (const float*)d_in[2];
    const float* Wv  = (const float*)d_in[3];
    const float* Wo  = (const float*)d_in[4];
    const float* W1  = (const float*)d_in[5];
    const float* b1  = (const float*)d_in[6];
    const float* W2  = (const float*)d_in[7];
    const float* b2  = (const float*)d_in[8];
    const float* g1  = (const float*)d_in[9];
    const float* be1 = (const float*)d_in[10];
    const float* g2  = (const float*)d_in[11];
    const float* be2 = (const float*)d_in[12];
    float* out = (float*)d_out;

    float *x2;
    __nv_bfloat16 *ah, *al, *qkvh, *qkvl, *fh, *fl, *wh, *wl;
    cudaGetSymbolAddress((void**)&x2,   g_x2);
    cudaGetSymbolAddress((void**)&ah,   g_a_hi);
    cudaGetSymbolAddress((void**)&al,   g_a_lo);
    cudaGetSymbolAddress((void**)&qkvh, g_qkv_hi);
    cudaGetSymbolAddress((void**)&qkvl, g_qkv_lo);
    cudaGetSymbolAddress((void**)&fh,   g_f_hi);
    cudaGetSymbolAddress((void**)&fl,   g_f_lo);
    cudaGetSymbolAddress((void**)&wh,   g_w_hi);
    cudaGetSymbolAddress((void**)&wl,   g_w_lo);

    const int GEMM_SMEM = 2 * STAGE_BYTES;
    cudaFuncSetAttribute(gemm_mma_kernel<1>, cudaFuncAttributeMaxDynamicSharedMemorySize, GEMM_SMEM);
    cudaFuncSetAttribute(gemm_mma_kernel<2>, cudaFuncAttributeMaxDynamicSharedMemorySize, GEMM_SMEM);
    cudaFuncSetAttribute(gemm_mma_kernel<3>, cudaFuncAttributeMaxDynamicSharedMemorySize, GEMM_SMEM);
    cudaFuncSetAttribute(gemm_mma_kernel<4>, cudaFuncAttributeMaxDynamicSharedMemorySize, GEMM_SMEM);
    const int ATTN_SMEM = 6 * ATT_TILE * 2;   // 55296
    cudaFuncSetAttribute(attention_mma_kernel, cudaFuncAttributeMaxDynamicSharedMemorySize, ATTN_SMEM);

    // 0) weight transpose + bf16 split
    {
        dim3 tb(32, 8);
        transpose_split_kernel<<<dim3(32,  32), tb>>>(Wq, wh + 0 * MEG, wl + 0 * MEG, 1024, 1024);
        transpose_split_kernel<<<dim3(32,  32), tb>>>(Wk, wh + 1 * MEG, wl + 1 * MEG, 1024, 1024);
        transpose_split_kernel<<<dim3(32,  32), tb>>>(Wv, wh + 2 * MEG, wl + 2 * MEG, 1024, 1024);
        transpose_split_kernel<<<dim3(32,  32), tb>>>(Wo, wh + 3 * MEG, wl + 3 * MEG, 1024, 1024);
        transpose_split_kernel<<<dim3(128, 32), tb>>>(W1, wh + 4 * MEG, wl + 4 * MEG, 1024, 4096);
        transpose_split_kernel<<<dim3(32, 128), tb>>>(W2, wh + 8 * MEG, wl + 8 * MEG, 4096, 1024);
    }

    // 1) LN1 -> bf16 split
    layernorm_split_kernel<<<MROWS, 256>>>(x, g1, be1, ah, al);

    // 2) fused QKV projection -> bf16 hi/lo [row][3072]
    {
        dim3 grid(QKVN / 128, MROWS / 128);
        gemm_mma_kernel<4><<<grid, 256, GEMM_SMEM>>>(ah, al, wh, wl,
            nullptr, nullptr, nullptr, qkvh, qkvl, MROWS, QKVN, DMODEL);
    }

    // 3) tensor-core causal attention -> ah/al
    {
        dim3 grid(SS / 64, BB * NHEADS);
        attention_mma_kernel<<<grid, 128, ATTN_SMEM>>>(qkvh, qkvl, ah, al);
    }

    // 4) output projection + residual(x) -> x2 (f32)
    {
        dim3 grid(DMODEL / 128, MROWS / 128);
        gemm_mma_kernel<1><<<grid, 256, GEMM_SMEM>>>(ah, al, wh + 3 * MEG, wl + 3 * MEG,
            nullptr, x, x2, nullptr, nullptr, MROWS, DMODEL, DMODEL);
    }

    // 5) LN2 -> bf16 split
    layernorm_split_kernel<<<MROWS, 256>>>(x2, g2, be2, ah, al);

    // 6) FFN1: relu(h2 @ W1 + b1) -> bf16 (fh/fl)
    {
        dim3 grid(DFF / 128, MROWS / 128);
        gemm_mma_kernel<2><<<grid, 256, GEMM_SMEM>>>(ah, al, wh + 4 * MEG, wl + 4 * MEG,
            b1, nullptr, nullptr, fh, fl, MROWS, DFF, DMODEL);
    }

    // 7) FFN2: ff @ W2 + b2 + x2 -> out
    {
        dim3 grid(DMODEL / 128, MROWS / 128);
        gemm_mma_kernel<3><<<grid, 256, GEMM_SMEM>>>(fh, fl, wh + 8 * MEG, wl + 8 * MEG,
            b2, x2, out, nullptr, nullptr, MROWS, DMODEL, DFF);
    }
}

// round 6
// speedup vs baseline: 2.6016x; 1.0883x over previous
#include <cuda_runtime.h>
#include <cuda_bf16.h>
#include <cstdint>
#include <math.h>

// ---------------------------------------------------------------------------
// Problem dims
// ---------------------------------------------------------------------------
#define BB      16
#define SS      512
#define DMODEL  1024
#define NHEADS  16
#define DK      64
#define DFF     4096
#define MROWS   (BB * SS)          // 8192
#define MEG     (1024 * 1024)
#define QKVN    3072

// ---------------------------------------------------------------------------
// Scratch (device globals)
// ---------------------------------------------------------------------------
__device__ float g_x2 [MROWS * DMODEL];
__device__ __nv_bfloat16 g_a_hi[MROWS * DMODEL];
__device__ __nv_bfloat16 g_a_lo[MROWS * DMODEL];
__device__ __nv_bfloat16 g_qkv_hi[MROWS * QKVN];
__device__ __nv_bfloat16 g_qkv_lo[MROWS * QKVN];
__device__ __nv_bfloat16 g_f_hi[MROWS * DFF];
__device__ __nv_bfloat16 g_f_lo[MROWS * DFF];
__device__ __nv_bfloat16 g_w_hi[12 * MEG];
__device__ __nv_bfloat16 g_w_lo[12 * MEG];
// offsets: Wq=0, Wk=1M, Wv=2M (contiguous [3072][1024]), Wo=3M, W1t=4M, W2t=8M

extern __shared__ char smem_raw[];

// ---------------------------------------------------------------------------
// PTX helpers
// ---------------------------------------------------------------------------
__device__ __forceinline__ uint32_t smem_u32(const void* p) {
    uint32_t a;
    asm("{ .reg .u64 t; cvta.to.shared.u64 t, %1; cvt.u32.u64 %0, t; }"
        : "=r"(a) : "l"(p));
    return a;
}
#define CP_ASYNC16(dst, src) \
    asm volatile("cp.async.cg.shared.global [%0], [%1], 16;" :: "r"(dst), "l"(src))
#define CP_COMMIT() asm volatile("cp.async.commit_group;" ::: "memory")
#define CP_WAIT(n)  asm volatile("cp.async.wait_group %0;" :: "n"(n) : "memory")

#define LDMATRIX_X4(r0, r1, r2, r3, addr) \
    asm volatile("ldmatrix.sync.aligned.m8n8.x4.shared.b16 {%0,%1,%2,%3}, [%4];" \
                 : "=r"(r0), "=r"(r1), "=r"(r2), "=r"(r3) : "r"(addr))
#define LDMATRIX_X4_T(r0, r1, r2, r3, addr) \
    asm volatile("ldmatrix.sync.aligned.m8n8.x4.trans.shared.b16 {%0,%1,%2,%3}, [%4];" \
                 : "=r"(r0), "=r"(r1), "=r"(r2), "=r"(r3) : "r"(addr))

#define MMA_BF16(c0, c1, c2, c3, a0, a1, a2, a3, b0, b1) \
    asm volatile("mma.sync.aligned.m16n8k16.row.col.f32.bf16.bf16.f32 " \
                 "{%0,%1,%2,%3}, {%4,%5,%6,%7}, {%8,%9}, {%0,%1,%2,%3};" \
                 : "+f"(c0), "+f"(c1), "+f"(c2), "+f"(c3) \
                 : "r"(a0), "r"(a1), "r"(a2), "r"(a3), "r"(b0), "r"(b1))

__device__ __forceinline__ __nv_bfloat16 bf_hi(float v) { return __float2bfloat16(v); }
__device__ __forceinline__ __nv_bfloat16 bf_lo(float v, __nv_bfloat16 h) {
    return __float2bfloat16(v - __bfloat162float(h));
}
__device__ __forceinline__ uint32_t pack2(__nv_bfloat16 x, __nv_bfloat16 y) {
    return (uint32_t)__bfloat16_as_ushort(x) |
           ((uint32_t)__bfloat16_as_ushort(y) << 16);
}

// ---------------------------------------------------------------------------
// Weight transpose + bf16 split
// ---------------------------------------------------------------------------
__global__ void __launch_bounds__(256) transpose_split_kernel(
    const float* __restrict__ W, __nv_bfloat16* __restrict__ oh,
    __nv_bfloat16* __restrict__ ol, int K, int N)
{
    __shared__ float t[32][33];
    const int tx = threadIdx.x, ty = threadIdx.y;
    const int n0 = blockIdx.x * 32;
    const int k0 = blockIdx.y * 32;
    #pragma unroll
    for (int j = 0; j < 32; j += 8)
        t[ty + j][tx] = W[(size_t)(k0 + ty + j) * N + n0 + tx];
    __syncthreads();
    #pragma unroll
    for (int j = 0; j < 32; j += 8) {
        const float v = t[tx][ty + j];
        const __nv_bfloat16 h = bf_hi(v);
        const size_t idx = (size_t)(n0 + ty + j) * K + k0 + tx;
        oh[idx] = h;
        ol[idx] = bf_lo(v, h);
    }
}

// ---------------------------------------------------------------------------
// LayerNorm -> bf16 hi/lo split
// ---------------------------------------------------------------------------
__global__ void __launch_bounds__(256) layernorm_split_kernel(
    const float* __restrict__ x, const float* __restrict__ g,
    const float* __restrict__ be, __nv_bfloat16* __restrict__ oh,
    __nv_bfloat16* __restrict__ ol)
{
    const int row = blockIdx.x;
    const int tid = threadIdx.x;
    const float4 v = *(const float4*)(x + (size_t)row * DMODEL + tid * 4);

    float s1 = v.x + v.y + v.z + v.w;
    float s2 = v.x * v.x + v.y * v.y + v.z * v.z + v.w * v.w;
    #pragma unroll
    for (int off = 16; off > 0; off >>= 1) {
        s1 += __shfl_xor_sync(0xffffffffu, s1, off);
        s2 += __shfl_xor_sync(0xffffffffu, s2, off);
    }
    __shared__ float sm1[8], sm2[8];
    const int w = tid >> 5, l = tid & 31;
    if (l == 0) { sm1[w] = s1; sm2[w] = s2; }
    __syncthreads();
    if (w == 0) {
        s1 = (l < 8) ? sm1[l] : 0.f;
        s2 = (l < 8) ? sm2[l] : 0.f;
        #pragma unroll
        for (int off = 4; off > 0; off >>= 1) {
            s1 += __shfl_xor_sync(0xffffffffu, s1, off);
            s2 += __shfl_xor_sync(0xffffffffu, s2, off);
        }
        if (l == 0) { sm1[0] = s1; sm2[0] = s2; }
    }
    __syncthreads();

    const float mu  = sm1[0] * (1.f / DMODEL);
    const float var = sm2[0] * (1.f / DMODEL) - mu * mu;
    const float inv = rsqrtf(var + 1e-5f);

    const float4 gv = *(const float4*)(g  + tid * 4);
    const float4 bv = *(const float4*)(be + tid * 4);
    float o[4];
    o[0] = (v.x - mu) * inv * gv.x + bv.x;
    o[1] = (v.y - mu) * inv * gv.y + bv.y;
    o[2] = (v.z - mu) * inv * gv.z + bv.z;
    o[3] = (v.w - mu) * inv * gv.w + bv.w;

    __align__(8) __nv_bfloat16 h4[4], l4[4];
    #pragma unroll
    for (int j = 0; j < 4; j++) { h4[j] = bf_hi(o[j]); l4[j] = bf_lo(o[j], h4[j]); }
    const size_t idx = (size_t)row * DMODEL + tid * 4;
    *(uint2*)(oh + idx) = *(uint2*)h4;
    *(uint2*)(ol + idx) = *(uint2*)l4;
}

// ---------------------------------------------------------------------------
// mma.sync bf16 split-3 GEMM, 4-tile residency:
//   per 64-K chunk load {Ah, Al, Bh, Bl} once, run 3 MMA passes from smem.
// CTA tile 128x128, 2-stage cp.async pipeline, 1 CTA/SM (147 KB smem).
// MODE: 1 = f32 +res | 2 = bf16 relu(+bias) | 3 = f32 +bias +res | 4 = bf16 plain
// ---------------------------------------------------------------------------
#define SM_STRIDE 72
#define SM_STRB   (SM_STRIDE * 2)
#define TILE_B    (128 * SM_STRB)          // 18432
#define STAGE4_B  (4 * TILE_B)             // 73728

template<int MODE>
__global__ void __launch_bounds__(256, 1) gemm_mma_kernel(
    const __nv_bfloat16* __restrict__ Ah, const __nv_bfloat16* __restrict__ Al,
    const __nv_bfloat16* __restrict__ Bh, const __nv_bfloat16* __restrict__ Bl,
    const float* __restrict__ bias, const float* __restrict__ res,
    float* __restrict__ Cf, __nv_bfloat16* __restrict__ Oh,
    __nv_bfloat16* __restrict__ Ol, int M, int N, int K)
{
    const uint32_t sbase = smem_u32(smem_raw);
    const int tid = threadIdx.x;
    const int wid = tid >> 5, lid = tid & 31;
    const int warp_m = wid & 3;
    const int warp_n = wid >> 2;
    const int bm = blockIdx.y * 128;
    const int bn = blockIdx.x * 128;

    const int segN = K >> 6;

    const __nv_bfloat16* srcs[4] = {
        Ah + (size_t)bm * K, Al + (size_t)bm * K,
        Bh + (size_t)bn * K, Bl + (size_t)bn * K };

    auto load_chunk = [&](int c) {
        const uint32_t st = sbase + (c & 1) * STAGE4_B;
        const int kk = c << 6;
        #pragma unroll
        for (int t = 0; t < 4; t++) {
            const __nv_bfloat16* g = srcs[t] + kk;
            const uint32_t tb = st + t * TILE_B;
            #pragma unroll
            for (int i = 0; i < 4; i++) {
                const int e = tid + 256 * i;       // 0..1023
                const int r = e >> 3;
                const int cch = e & 7;
                CP_ASYNC16(tb + r * SM_STRB + cch * 16,
                           (const void*)(g + (size_t)r * K + cch * 8));
            }
        }
        CP_COMMIT();
    };

    float acc[2][8][4];
    #pragma unroll
    for (int mi = 0; mi < 2; mi++)
        #pragma unroll
        for (int ni = 0; ni < 8; ni++)
            #pragma unroll
            for (int q = 0; q < 4; q++) acc[mi][ni][q] = 0.f;

    const int a_row_off = (lid & 7) + ((lid >> 3) & 1) * 8;
    const int a_k_off   = ((lid >> 4) & 1) * 8;
    const int b_n_off   = (lid & 7) + ((lid >> 4) & 1) * 8;
    const int b_k_off   = ((lid >> 3) & 1) * 8;

    load_chunk(0);

    for (int c = 0; c < segN; c++) {
        if (c + 1 < segN) load_chunk(c + 1);
        if (c + 1 < segN) { CP_WAIT(1); } else { CP_WAIT(0); }
        __syncthreads();

        const uint32_t st  = sbase + (c & 1) * STAGE4_B;
        const uint32_t sAh = st;
        const uint32_t sAl = st + TILE_B;
        const uint32_t sBh = st + 2 * TILE_B;
        const uint32_t sBl = st + 3 * TILE_B;

        #pragma unroll
        for (int k16 = 0; k16 < 64; k16 += 16) {
            uint32_t ah[2][4], al[2][4];
            #pragma unroll
            for (int mi = 0; mi < 2; mi++) {
                const uint32_t roff =
                    (warp_m * 32 + mi * 16 + a_row_off) * SM_STRB + (k16 + a_k_off) * 2;
                LDMATRIX_X4(ah[mi][0], ah[mi][1], ah[mi][2], ah[mi][3], sAh + roff);
                LDMATRIX_X4(al[mi][0], al[mi][1], al[mi][2], al[mi][3], sAl + roff);
            }
            uint32_t bh[8][2], bl[8][2];
            #pragma unroll
            for (int np = 0; np < 4; np++) {
                const uint32_t roff =
                    (warp_n * 64 + np * 16 + b_n_off) * SM_STRB + (k16 + b_k_off) * 2;
                uint32_t r0, r1, r2, r3;
                LDMATRIX_X4(r0, r1, r2, r3, sBh + roff);
                bh[2 * np][0] = r0; bh[2 * np][1] = r1;
                bh[2 * np + 1][0] = r2; bh[2 * np + 1][1] = r3;
                LDMATRIX_X4(r0, r1, r2, r3, sBl + roff);
                bl[2 * np][0] = r0; bl[2 * np][1] = r1;
                bl[2 * np + 1][0] = r2; bl[2 * np + 1][1] = r3;
            }
            #pragma unroll
            for (int mi = 0; mi < 2; mi++)
                #pragma unroll
                for (int ni = 0; ni < 8; ni++) {
                    MMA_BF16(acc[mi][ni][0], acc[mi][ni][1],
                             acc[mi][ni][2], acc[mi][ni][3],
                             ah[mi][0], ah[mi][1], ah[mi][2], ah[mi][3],
                             bh[ni][0], bh[ni][1]);
                    MMA_BF16(acc[mi][ni][0], acc[mi][ni][1],
                             acc[mi][ni][2], acc[mi][ni][3],
                             ah[mi][0], ah[mi][1], ah[mi][2], ah[mi][3],
                             bl[ni][0], bl[ni][1]);
                    MMA_BF16(acc[mi][ni][0], acc[mi][ni][1],
                             acc[mi][ni][2], acc[mi][ni][3],
                             al[mi][0], al[mi][1], al[mi][2], al[mi][3],
                             bh[ni][0], bh[ni][1]);
                }
        }
        __syncthreads();
    }

    const int lr = lid >> 2;
    const int lc = (lid & 3) * 2;
    #pragma unroll
    for (int mi = 0; mi < 2; mi++) {
        #pragma unroll
        for (int ni = 0; ni < 8; ni++) {
            const int col = bn + warp_n * 64 + ni * 8 + lc;
            #pragma unroll
            for (int half = 0; half < 2; half++) {
                const int row = bm + warp_m * 32 + mi * 16 + lr + half * 8;
                const size_t off = (size_t)row * N + col;
                float v0 = acc[mi][ni][2 * half];
                float v1 = acc[mi][ni][2 * half + 1];
                if (MODE == 2 || MODE == 4) {
                    if (MODE == 2) {
                        v0 = fmaxf(v0 + bias[col], 0.f);
                        v1 = fmaxf(v1 + bias[col + 1], 0.f);
                    }
                    __nv_bfloat16 h0 = bf_hi(v0), h1 = bf_hi(v1);
                    *(uint32_t*)(Oh + off) = pack2(h0, h1);
                    *(uint32_t*)(Ol + off) = pack2(bf_lo(v0, h0), bf_lo(v1, h1));
                } else {
                    if (MODE == 3) { v0 += bias[col]; v1 += bias[col + 1]; }
                    const float2 rr = *(const float2*)(res + off);
                    v0 += rr.x; v1 += rr.y;
                    *(float2*)(Cf + off) = make_float2(v0, v1);
                }
            }
        }
    }
}

// ---------------------------------------------------------------------------
// Tensor-core causal flash attention, split-3 bf16, 128 q-rows per block.
// 256 threads (8 warps); warp w owns rows 16w..16w+15 of the 128-row tile.
// K/V tiles (64 kpos) double-buffered via cp.async; fully-masked warps skip.
// smem: Qh Ql [128][72] + 2 stages x {Kh,Kl,Vh,Vl}[64][72]  = 110592 B
// ---------------------------------------------------------------------------
#define ATT_STR  72
#define ATT_STRB (ATT_STR * 2)
#define ATT_QT_B (128 * ATT_STRB)          // 18432
#define ATT_KV_B (64 * ATT_STRB)           // 9216
#define ATT_ST_B (4 * ATT_KV_B)            // 36864

__global__ void __launch_bounds__(256) attention_mma_kernel(
    const __nv_bfloat16* __restrict__ QKVh, const __nv_bfloat16* __restrict__ QKVl,
    __nv_bfloat16* __restrict__ Oh, __nv_bfloat16* __restrict__ Ol)
{
    const uint32_t sbase = smem_u32(smem_raw);
    const uint32_t sQh = sbase;
    const uint32_t sQl = sbase + ATT_QT_B;

    const int qt = blockIdx.x;              // 0..3 (128-row q tiles)
    const int bh = blockIdx.y;
    const int b  = bh >> 4;
    const int h  = bh & 15;
    const int q0 = qt * 128;
    const size_t rowbase = (size_t)b * SS;

    const int tid = threadIdx.x;
    const int w   = tid >> 5;
    const int lid = tid & 31;
    const int lr  = lid >> 2;
    const int lq  = lid & 3;

    const int a_row_off = (lid & 7) + ((lid >> 3) & 1) * 8;
    const int a_k_off   = ((lid >> 4) & 1) * 8;
    const int b_n_off   = (lid & 7) + ((lid >> 4) & 1) * 8;
    const int b_k_off   = ((lid >> 3) & 1) * 8;
    const int v_row_off = (lid & 7) + ((lid >> 3) & 1) * 8;
    const int v_col_off = ((lid >> 4) & 1) * 8;

    // ---- load Q tiles (hi/lo), scaled by 0.125 (exact in bf16) ----
    {
        const size_t qcol = (size_t)h * DK;
        #pragma unroll
        for (int i = 0; i < 4; i++) {
            const int e = tid + 256 * i;       // 0..1023
            const int r = e >> 3;
            const int c = e & 7;
            const size_t g = (rowbase + q0 + r) * QKVN + qcol + c * 8;
            const uint32_t sm = r * ATT_STRB + c * 16;
            uint4 vh = *(const uint4*)(QKVh + g);
            uint4 vl = *(const uint4*)(QKVl + g);
            __nv_bfloat16* ph = (__nv_bfloat16*)&vh;
            __nv_bfloat16* pl = (__nv_bfloat16*)&vl;
            #pragma unroll
            for (int j = 0; j < 8; j++) {
                ph[j] = __float2bfloat16(__bfloat162float(ph[j]) * 0.125f);
                pl[j] = __float2bfloat16(__bfloat162float(pl[j]) * 0.125f);
            }
            *(uint4*)(smem_raw + (sQh - sbase) + sm) = vh;
            *(uint4*)(smem_raw + (sQl - sbase) + sm) = vl;
        }
    }

    auto kv_load = [&](int kt) {
        const uint32_t st = sbase + 2 * ATT_QT_B + (kt & 1) * ATT_ST_B;
        const size_t kcol = 1024 + (size_t)h * DK;
        const size_t vcol = 2048 + (size_t)h * DK;
        #pragma unroll
        for (int i = 0; i < 2; i++) {
            const int e = tid + 256 * i;       // 0..511
            const int r = e >> 3;
            const int c = e & 7;
            const size_t grow = (rowbase + kt * 64 + r) * QKVN;
            const uint32_t sm = r * ATT_STRB + c * 16;
            CP_ASYNC16(st + 0 * ATT_KV_B + sm, (const void*)(QKVh + grow + kcol + c * 8));
            CP_ASYNC16(st + 1 * ATT_KV_B + sm, (const void*)(QKVl + grow + kcol + c * 8));
            CP_ASYNC16(st + 2 * ATT_KV_B + sm, (const void*)(QKVh + grow + vcol + c * 8));
            CP_ASYNC16(st + 3 * ATT_KV_B + sm, (const void*)(QKVl + grow + vcol + c * 8));
        }
        CP_COMMIT();
    };

    float m0 = -1e30f, m1 = -1e30f, l0 = 0.f, l1 = 0.f;
    float o[8][4];
    #pragma unroll
    for (int ni = 0; ni < 8; ni++)
        #pragma unroll
        for (int q = 0; q < 4; q++) o[ni][q] = 0.f;

    const int NT = 2 * qt + 2;              // K tiles covering keys <= q0+127
    kv_load(0);

    for (int kt = 0; kt < NT; kt++) {
        if (kt + 1 < NT) kv_load(kt + 1);
        if (kt + 1 < NT) { CP_WAIT(1); } else { CP_WAIT(0); }
        __syncthreads();

        const int wrow_min = q0 + w * 16;       // warp's lowest q row
        const bool active  = (64 * kt <= wrow_min + 15);
        if (active) {
            const uint32_t st  = sbase + 2 * ATT_QT_B + (kt & 1) * ATT_ST_B;
            const uint32_t sKh = st;
            const uint32_t sKl = st + ATT_KV_B;
            const uint32_t sVh = st + 2 * ATT_KV_B;
            const uint32_t sVl = st + 3 * ATT_KV_B;

            // ---- S = Q K^T (split-3) ----
            float s[8][4];
            #pragma unroll
            for (int ni = 0; ni < 8; ni++)
                #pragma unroll
                for (int q = 0; q < 4; q++) s[ni][q] = 0.f;

            const uint32_t QT[3] = { sQh, sQh, sQl };
            const uint32_t KT[3] = { sKh, sKl, sKh };
            #pragma unroll
            for (int p = 0; p < 3; p++) {
                #pragma unroll
                for (int k16 = 0; k16 < 64; k16 += 16) {
                    uint32_t a0, a1, a2, a3;
                    LDMATRIX_X4(a0, a1, a2, a3,
                        QT[p] + (w * 16 + a_row_off) * ATT_STRB + (k16 + a_k_off) * 2);
                    uint32_t bb[8][2];
                    #pragma unroll
                    for (int np = 0; np < 4; np++) {
                        uint32_t r0, r1, r2, r3;
                        LDMATRIX_X4(r0, r1, r2, r3,
                            KT[p] + (np * 16 + b_n_off) * ATT_STRB + (k16 + b_k_off) * 2);
                        bb[2 * np][0] = r0; bb[2 * np][1] = r1;
                        bb[2 * np + 1][0] = r2; bb[2 * np + 1][1] = r3;
                    }
                    #pragma unroll
                    for (int ni = 0; ni < 8; ni++)
                        MMA_BF16(s[ni][0], s[ni][1], s[ni][2], s[ni][3],
                                 a0, a1, a2, a3, bb[ni][0], bb[ni][1]);
                }
            }

            // ---- causal mask (global indices); needed only near diagonal ----
            if (64 * kt + 63 > wrow_min) {
                const int r0g = wrow_min + lr;
                const int r1g = r0g + 8;
                #pragma unroll
                for (int ni = 0; ni < 8; ni++) {
                    const int c0 = 64 * kt + ni * 8 + lq * 2;
                    if (c0 > r0g)     s[ni][0] = -1e30f;
                    if (c0 + 1 > r0g) s[ni][1] = -1e30f;
                    if (c0 > r1g)     s[ni][2] = -1e30f;
                    if (c0 + 1 > r1g) s[ni][3] = -1e30f;
                }
            }

            // ---- online softmax ----
            float mt0 = -1e30f, mt1 = -1e30f;
            #pragma unroll
            for (int ni = 0; ni < 8; ni++) {
                mt0 = fmaxf(mt0, fmaxf(s[ni][0], s[ni][1]));
                mt1 = fmaxf(mt1, fmaxf(s[ni][2], s[ni][3]));
            }
            mt0 = fmaxf(mt0, __shfl_xor_sync(0xffffffffu, mt0, 1));
            mt0 = fmaxf(mt0, __shfl_xor_sync(0xffffffffu, mt0, 2));
            mt1 = fmaxf(mt1, __shfl_xor_sync(0xffffffffu, mt1, 1));
            mt1 = fmaxf(mt1, __shfl_xor_sync(0xffffffffu, mt1, 2));
            const float mn0 = fmaxf(m0, mt0), mn1 = fmaxf(m1, mt1);
            const float cr0 = __expf(m0 - mn0), cr1 = __expf(m1 - mn1);
            float rs0 = 0.f, rs1 = 0.f;
            #pragma unroll
            for (int ni = 0; ni < 8; ni++) {
                s[ni][0] = __expf(s[ni][0] - mn0); rs0 += s[ni][0];
                s[ni][1] = __expf(s[ni][1] - mn0); rs0 += s[ni][1];
                s[ni][2] = __expf(s[ni][2] - mn1); rs1 += s[ni][2];
                s[ni][3] = __expf(s[ni][3] - mn1); rs1 += s[ni][3];
            }
            rs0 += __shfl_xor_sync(0xffffffffu, rs0, 1);
            rs0 += __shfl_xor_sync(0xffffffffu, rs0, 2);
            rs1 += __shfl_xor_sync(0xffffffffu, rs1, 1);
            rs1 += __shfl_xor_sync(0xffffffffu, rs1, 2);
            l0 = l0 * cr0 + rs0;  l1 = l1 * cr1 + rs1;
            m0 = mn0;  m1 = mn1;
            #pragma unroll
            for (int ni = 0; ni < 8; ni++) {
                o[ni][0] *= cr0; o[ni][1] *= cr0;
                o[ni][2] *= cr1; o[ni][3] *= cr1;
            }

            // ---- O += P V (split-3) ----
            #pragma unroll
            for (int j = 0; j < 4; j++) {
                const int t0 = 2 * j, t1 = 2 * j + 1;
                __nv_bfloat16 h00 = bf_hi(s[t0][0]), h01 = bf_hi(s[t0][1]);
                __nv_bfloat16 h02 = bf_hi(s[t0][2]), h03 = bf_hi(s[t0][3]);
                __nv_bfloat16 h10 = bf_hi(s[t1][0]), h11 = bf_hi(s[t1][1]);
                __nv_bfloat16 h12 = bf_hi(s[t1][2]), h13 = bf_hi(s[t1][3]);
                const uint32_t ah0 = pack2(h00, h01);
                const uint32_t ah1 = pack2(h02, h03);
                const uint32_t ah2 = pack2(h10, h11);
                const uint32_t ah3 = pack2(h12, h13);
                const uint32_t al0 = pack2(bf_lo(s[t0][0], h00), bf_lo(s[t0][1], h01));
                const uint32_t al1 = pack2(bf_lo(s[t0][2], h02), bf_lo(s[t0][3], h03));
                const uint32_t al2 = pack2(bf_lo(s[t1][0], h10), bf_lo(s[t1][1], h11));
                const uint32_t al3 = pack2(bf_lo(s[t1][2], h12), bf_lo(s[t1][3], h13));

                #pragma unroll
                for (int np = 0; np < 4; np++) {
                    uint32_t bh0, bh1, bh2, bh3, bl0, bl1, bl2, bl3;
                    const uint32_t vaddr =
                        (j * 16 + v_row_off) * ATT_STRB + (np * 16 + v_col_off) * 2;
                    LDMATRIX_X4_T(bh0, bh1, bh2, bh3, sVh + vaddr);
                    LDMATRIX_X4_T(bl0, bl1, bl2, bl3, sVl + vaddr);
                    MMA_BF16(o[2*np][0], o[2*np][1], o[2*np][2], o[2*np][3],
                             ah0, ah1, ah2, ah3, bh0, bh1);
                    MMA_BF16(o[2*np+1][0], o[2*np+1][1], o[2*np+1][2], o[2*np+1][3],
                             ah0, ah1, ah2, ah3, bh2, bh3);
                    MMA_BF16(o[2*np][0], o[2*np][1], o[2*np][2], o[2*np][3],
                             ah0, ah1, ah2, ah3, bl0, bl1);
                    MMA_BF16(o[2*np+1][0], o[2*np+1][1], o[2*np+1][2], o[2*np+1][3],
                             ah0, ah1, ah2, ah3, bl2, bl3);
                    MMA_BF16(o[2*np][0], o[2*np][1], o[2*np][2], o[2*np][3],
                             al0, al1, al2, al3, bh0, bh1);
                    MMA_BF16(o[2*np+1][0], o[2*np+1][1], o[2*np+1][2], o[2*np+1][3],
                             al0, al1, al2, al3, bh2, bh3);
                }
            }
        }
        __syncthreads();
    }

    // ---- finalize ----
    const float inv0 = 1.f / l0, inv1 = 1.f / l1;
    #pragma unroll
    for (int ni = 0; ni < 8; ni++) {
        const int col = h * DK + ni * 8 + lq * 2;
        {
            const size_t off = (rowbase + q0 + w * 16 + lr) * DMODEL + col;
            const float f0 = o[ni][0] * inv0, f1 = o[ni][1] * inv0;
            __nv_bfloat16 h0 = bf_hi(f0), h1 = bf_hi(f1);
            *(uint32_t*)(Oh + off) = pack2(h0, h1);
            *(uint32_t*)(Ol + off) = pack2(bf_lo(f0, h0), bf_lo(f1, h1));
        }
        {
            const size_t off = (rowbase + q0 + w * 16 + lr + 8) * DMODEL + col;
            const float f0 = o[ni][2] * inv1, f1 = o[ni][3] * inv1;
            __nv_bfloat16 h0 = bf_hi(f0), h1 = bf_hi(f1);
            *(uint32_t*)(Oh + off) = pack2(h0, h1);
            *(uint32_t*)(Ol + off) = pack2(bf_lo(f0, h0), bf_lo(f1, h1));
        }
    }
}

// ---------------------------------------------------------------------------
// Launch
// ---------------------------------------------------------------------------
extern "C" void kernel_launch(void* const* d_in, const int* in_sizes, int n_in,
                              void* d_out, int out_size)
{
    const float* x   = (const float*)d_in[0];
    const float* Wq  = (const float*)d_in[1];
    const float* Wk  = (const float*)d_in[2];
    const float* Wv  = (const float*)d_in[3];
    const float* Wo  = (const float*)d_in[4];
    const float* W1  = (const float*)d_in[5];
    const float* b1  = (const float*)d_in[6];
    const float* W2  = (const float*)d_in[7];
    const float* b2  = (const float*)d_in[8];
    const float* g1  = (const float*)d_in[9];
    const float* be1 = (const float*)d_in[10];
    const float* g2  = (const float*)d_in[11];
    const float* be2 = (const float*)d_in[12];
    float* out = (float*)d_out;

    float *x2;
    __nv_bfloat16 *ah, *al, *qkvh, *qkvl, *fh, *fl, *wh, *wl;
    cudaGetSymbolAddress((void**)&x2,   g_x2);
    cudaGetSymbolAddress((void**)&ah,   g_a_hi);
    cudaGetSymbolAddress((void**)&al,   g_a_lo);
    cudaGetSymbolAddress((void**)&qkvh, g_qkv_hi);
    cudaGetSymbolAddress((void**)&qkvl, g_qkv_lo);
    cudaGetSymbolAddress((void**)&fh,   g_f_hi);
    cudaGetSymbolAddress((void**)&fl,   g_f_lo);
    cudaGetSymbolAddress((void**)&wh,   g_w_hi);
    cudaGetSymbolAddress((void**)&wl,   g_w_lo);

    const int GEMM_SMEM = 2 * STAGE4_B;   // 147456
    cudaFuncSetAttribute(gemm_mma_kernel<1>, cudaFuncAttributeMaxDynamicSharedMemorySize, GEMM_SMEM);
    cudaFuncSetAttribute(gemm_mma_kernel<2>, cudaFuncAttributeMaxDynamicSharedMemorySize, GEMM_SMEM);
    cudaFuncSetAttribute(gemm_mma_kernel<3>, cudaFuncAttributeMaxDynamicSharedMemorySize, GEMM_SMEM);
    cudaFuncSetAttribute(gemm_mma_kernel<4>, cudaFuncAttributeMaxDynamicSharedMemorySize, GEMM_SMEM);
    const int ATTN_SMEM = 2 * ATT_QT_B + 2 * ATT_ST_B;   // 110592
    cudaFuncSetAttribute(attention_mma_kernel, cudaFuncAttributeMaxDynamicSharedMemorySize, ATTN_SMEM);

    // 0) weight transpose + bf16 split
    {
        dim3 tb(32, 8);
        transpose_split_kernel<<<dim3(32,  32), tb>>>(Wq, wh + 0 * MEG, wl + 0 * MEG, 1024, 1024);
        transpose_split_kernel<<<dim3(32,  32), tb>>>(Wk, wh + 1 * MEG, wl + 1 * MEG, 1024, 1024);
        transpose_split_kernel<<<dim3(32,  32), tb>>>(Wv, wh + 2 * MEG, wl + 2 * MEG, 1024, 1024);
        transpose_split_kernel<<<dim3(32,  32), tb>>>(Wo, wh + 3 * MEG, wl + 3 * MEG, 1024, 1024);
        transpose_split_kernel<<<dim3(128, 32), tb>>>(W1, wh + 4 * MEG, wl + 4 * MEG, 1024, 4096);
        transpose_split_kernel<<<dim3(32, 128), tb>>>(W2, wh + 8 * MEG, wl + 8 * MEG, 4096, 1024);
    }

    // 1) LN1 -> bf16 split
    layernorm_split_kernel<<<MROWS, 256>>>(x, g1, be1, ah, al);

    // 2) fused QKV projection -> bf16 hi/lo [row][3072]
    {
        dim3 grid(QKVN / 128, MROWS / 128);
        gemm_mma_kernel<4><<<grid, 256, GEMM_SMEM>>>(ah, al, wh, wl,
            nullptr, nullptr, nullptr, qkvh, qkvl, MROWS, QKVN, DMODEL);
    }

    // 3) tensor-core causal attention -> ah/al
    {
        dim3 grid(SS / 128, BB * NHEADS);
        attention_mma_kernel<<<grid, 256, ATTN_SMEM>>>(qkvh, qkvl, ah, al);
    }

    // 4) output projection + residual(x) -> x2 (f32)
    {
        dim3 grid(DMODEL / 128, MROWS / 128);
        gemm_mma_kernel<1><<<grid, 256, GEMM_SMEM>>>(ah, al, wh + 3 * MEG, wl + 3 * MEG,
            nullptr, x, x2, nullptr, nullptr, MROWS, DMODEL, DMODEL);
    }

    // 5) LN2 -> bf16 split
    layernorm_split_kernel<<<MROWS, 256>>>(x2, g2, be2, ah, al);

    // 6) FFN1: relu(h2 @ W1 + b1) -> bf16 (fh/fl)
    {
        dim3 grid(DFF / 128, MROWS / 128);
        gemm_mma_kernel<2><<<grid, 256, GEMM_SMEM>>>(ah, al, wh + 4 * MEG, wl + 4 * MEG,
            b1, nullptr, nullptr, fh, fl, MROWS, DFF, DMODEL);
    }

    // 7) FFN2: ff @ W2 + b2 + x2 -> out
    {
        dim3 grid(DMODEL / 128, MROWS / 128);
        gemm_mma_kernel<3><<<grid, 256, GEMM_SMEM>>>(fh, fl, wh + 8 * MEG, wl + 8 * MEG,
            b2, x2, out, nullptr, nullptr, MROWS, DMODEL, DFF);
    }
}

// round 7
// speedup vs baseline: 4.3049x; 1.6547x over previous
#include <cuda_runtime.h>
#include <cuda_bf16.h>
#include <cuda_fp16.h>
#include <cstdint>
#include <math.h>

// ---------------------------------------------------------------------------
// Problem dims
// ---------------------------------------------------------------------------
#define BB      16
#define SS      512
#define DMODEL  1024
#define NHEADS  16
#define DK      64
#define DFF     4096
#define MROWS   (BB * SS)          // 8192
#define MEG     (1024 * 1024)
#define QKVN    3072

// ---------------------------------------------------------------------------
// Scratch (device globals)
// ---------------------------------------------------------------------------
__device__ float g_x2 [MROWS * DMODEL];
__device__ __nv_bfloat16 g_a_hi[MROWS * DMODEL];   // ln1/att out (hi) | ln2 fp16
__device__ __nv_bfloat16 g_a_lo[MROWS * DMODEL];
__device__ __nv_bfloat16 g_qkv_hi[MROWS * QKVN];
__device__ __nv_bfloat16 g_qkv_lo[MROWS * QKVN];
__device__ __half        g_ffh [MROWS * DFF];      // ffn intermediate (fp16)
__device__ __nv_bfloat16 g_w_hi[12 * MEG];         // Wq..Wo bf16-hi; W1t/W2t fp16
__device__ __nv_bfloat16 g_w_lo[4 * MEG];          // Wq..Wo bf16-lo
// g_w_hi offsets: Wq=0, Wk=1M, Wv=2M, Wo=3M, W1t=4M(4M fp16), W2t=8M(4M fp16)

extern __shared__ char smem_raw[];

// ---------------------------------------------------------------------------
// PTX helpers
// ---------------------------------------------------------------------------
__device__ __forceinline__ uint32_t smem_u32(const void* p) {
    uint32_t a;
    asm("{ .reg .u64 t; cvta.to.shared.u64 t, %1; cvt.u32.u64 %0, t; }"
        : "=r"(a) : "l"(p));
    return a;
}
#define CP_ASYNC16(dst, src) \
    asm volatile("cp.async.cg.shared.global [%0], [%1], 16;" :: "r"(dst), "l"(src))
#define CP_COMMIT() asm volatile("cp.async.commit_group;" ::: "memory")
#define CP_WAIT(n)  asm volatile("cp.async.wait_group %0;" :: "n"(n) : "memory")

#define LDMATRIX_X4(r0, r1, r2, r3, addr) \
    asm volatile("ldmatrix.sync.aligned.m8n8.x4.shared.b16 {%0,%1,%2,%3}, [%4];" \
                 : "=r"(r0), "=r"(r1), "=r"(r2), "=r"(r3) : "r"(addr))
#define LDMATRIX_X4_T(r0, r1, r2, r3, addr) \
    asm volatile("ldmatrix.sync.aligned.m8n8.x4.trans.shared.b16 {%0,%1,%2,%3}, [%4];" \
                 : "=r"(r0), "=r"(r1), "=r"(r2), "=r"(r3) : "r"(addr))

#define MMA_BF16(c0, c1, c2, c3, a0, a1, a2, a3, b0, b1) \
    asm volatile("mma.sync.aligned.m16n8k16.row.col.f32.bf16.bf16.f32 " \
                 "{%0,%1,%2,%3}, {%4,%5,%6,%7}, {%8,%9}, {%0,%1,%2,%3};" \
                 : "+f"(c0), "+f"(c1), "+f"(c2), "+f"(c3) \
                 : "r"(a0), "r"(a1), "r"(a2), "r"(a3), "r"(b0), "r"(b1))
#define MMA_FP16(c0, c1, c2, c3, a0, a1, a2, a3, b0, b1) \
    asm volatile("mma.sync.aligned.m16n8k16.row.col.f32.f16.f16.f32 " \
                 "{%0,%1,%2,%3}, {%4,%5,%6,%7}, {%8,%9}, {%0,%1,%2,%3};" \
                 : "+f"(c0), "+f"(c1), "+f"(c2), "+f"(c3) \
                 : "r"(a0), "r"(a1), "r"(a2), "r"(a3), "r"(b0), "r"(b1))

__device__ __forceinline__ __nv_bfloat16 bf_hi(float v) { return __float2bfloat16(v); }
__device__ __forceinline__ __nv_bfloat16 bf_lo(float v, __nv_bfloat16 h) {
    return __float2bfloat16(v - __bfloat162float(h));
}
__device__ __forceinline__ uint32_t pack2(__nv_bfloat16 x, __nv_bfloat16 y) {
    return (uint32_t)__bfloat16_as_ushort(x) |
           ((uint32_t)__bfloat16_as_ushort(y) << 16);
}
__device__ __forceinline__ uint32_t pack2h(__half x, __half y) {
    return (uint32_t)__half_as_ushort(x) |
           ((uint32_t)__half_as_ushort(y) << 16);
}

// ---------------------------------------------------------------------------
// Weight transpose: FP16=0 -> bf16 hi/lo; FP16=1 -> fp16 single (into oh)
// ---------------------------------------------------------------------------
template<int FP16>
__global__ void __launch_bounds__(256) transpose_split_kernel(
    const float* __restrict__ W, __nv_bfloat16* __restrict__ oh,
    __nv_bfloat16* __restrict__ ol, int K, int N)
{
    __shared__ float t[32][33];
    const int tx = threadIdx.x, ty = threadIdx.y;
    const int n0 = blockIdx.x * 32;
    const int k0 = blockIdx.y * 32;
    #pragma unroll
    for (int j = 0; j < 32; j += 8)
        t[ty + j][tx] = W[(size_t)(k0 + ty + j) * N + n0 + tx];
    __syncthreads();
    #pragma unroll
    for (int j = 0; j < 32; j += 8) {
        const float v = t[tx][ty + j];
        const size_t idx = (size_t)(n0 + ty + j) * K + k0 + tx;
        if (FP16) {
            ((__half*)oh)[idx] = __float2half(v);
        } else {
            const __nv_bfloat16 h = bf_hi(v);
            oh[idx] = h;
            ol[idx] = bf_lo(v, h);
        }
    }
}

// ---------------------------------------------------------------------------
// LayerNorm: FP16=0 -> bf16 hi/lo split; FP16=1 -> fp16 single (into oh)
// ---------------------------------------------------------------------------
template<int FP16>
__global__ void __launch_bounds__(256) layernorm_split_kernel(
    const float* __restrict__ x, const float* __restrict__ g,
    const float* __restrict__ be, __nv_bfloat16* __restrict__ oh,
    __nv_bfloat16* __restrict__ ol)
{
    const int row = blockIdx.x;
    const int tid = threadIdx.x;
    const float4 v = *(const float4*)(x + (size_t)row * DMODEL + tid * 4);

    float s1 = v.x + v.y + v.z + v.w;
    float s2 = v.x * v.x + v.y * v.y + v.z * v.z + v.w * v.w;
    #pragma unroll
    for (int off = 16; off > 0; off >>= 1) {
        s1 += __shfl_xor_sync(0xffffffffu, s1, off);
        s2 += __shfl_xor_sync(0xffffffffu, s2, off);
    }
    __shared__ float sm1[8], sm2[8];
    const int w = tid >> 5, l = tid & 31;
    if (l == 0) { sm1[w] = s1; sm2[w] = s2; }
    __syncthreads();
    if (w == 0) {
        s1 = (l < 8) ? sm1[l] : 0.f;
        s2 = (l < 8) ? sm2[l] : 0.f;
        #pragma unroll
        for (int off = 4; off > 0; off >>= 1) {
            s1 += __shfl_xor_sync(0xffffffffu, s1, off);
            s2 += __shfl_xor_sync(0xffffffffu, s2, off);
        }
        if (l == 0) { sm1[0] = s1; sm2[0] = s2; }
    }
    __syncthreads();

    const float mu  = sm1[0] * (1.f / DMODEL);
    const float var = sm2[0] * (1.f / DMODEL) - mu * mu;
    const float inv = rsqrtf(var + 1e-5f);

    const float4 gv = *(const float4*)(g  + tid * 4);
    const float4 bv = *(const float4*)(be + tid * 4);
    float o[4];
    o[0] = (v.x - mu) * inv * gv.x + bv.x;
    o[1] = (v.y - mu) * inv * gv.y + bv.y;
    o[2] = (v.z - mu) * inv * gv.z + bv.z;
    o[3] = (v.w - mu) * inv * gv.w + bv.w;

    const size_t idx = (size_t)row * DMODEL + tid * 4;
    if (FP16) {
        __align__(8) __half h4[4];
        #pragma unroll
        for (int j = 0; j < 4; j++) h4[j] = __float2half(o[j]);
        *(uint2*)((__half*)oh + idx) = *(uint2*)h4;
    } else {
        __align__(8) __nv_bfloat16 h4[4], l4[4];
        #pragma unroll
        for (int j = 0; j < 4; j++) { h4[j] = bf_hi(o[j]); l4[j] = bf_lo(o[j], h4[j]); }
        *(uint2*)(oh + idx) = *(uint2*)h4;
        *(uint2*)(ol + idx) = *(uint2*)l4;
    }
}

// ---------------------------------------------------------------------------
// mma.sync GEMM. SPLIT3=true: bf16 split-3 (4-tile residency).
//                SPLIT3=false: fp16 single pass (2-tile residency, 2 CTA/SM).
// MODE: 1 = f32 +res | 3 = f32 +bias +res | 4 = bf16 hi/lo plain
//       5 = fp16 single, relu(+bias)
// ---------------------------------------------------------------------------
#define SM_STRIDE 72
#define SM_STRB   (SM_STRIDE * 2)
#define TILE_B    (128 * SM_STRB)          // 18432

template<int MODE, bool SPLIT3>
__global__ void __launch_bounds__(256) gemm_mma_kernel(
    const __nv_bfloat16* __restrict__ Ah, const __nv_bfloat16* __restrict__ Al,
    const __nv_bfloat16* __restrict__ Bh, const __nv_bfloat16* __restrict__ Bl,
    const float* __restrict__ bias, const float* __restrict__ res,
    float* __restrict__ Cf, __nv_bfloat16* __restrict__ Oh,
    __nv_bfloat16* __restrict__ Ol, int M, int N, int K)
{
    constexpr int NT_TILES = SPLIT3 ? 4 : 2;
    constexpr uint32_t STAGE_B = NT_TILES * TILE_B;

    const uint32_t sbase = smem_u32(smem_raw);
    const int tid = threadIdx.x;
    const int wid = tid >> 5, lid = tid & 31;
    const int warp_m = wid & 3;
    const int warp_n = wid >> 2;
    const int bm = blockIdx.y * 128;
    const int bn = blockIdx.x * 128;

    const int segN = K >> 6;

    const __nv_bfloat16* srcs[NT_TILES];
    srcs[0] = Ah + (size_t)bm * K;
    if (SPLIT3) {
        srcs[1] = Al + (size_t)bm * K;
        srcs[2] = Bh + (size_t)bn * K;
        srcs[3] = Bl + (size_t)bn * K;
    } else {
        srcs[1] = Bh + (size_t)bn * K;
    }

    auto load_chunk = [&](int c) {
        const uint32_t st = sbase + (c & 1) * STAGE_B;
        const int kk = c << 6;
        #pragma unroll
        for (int t = 0; t < NT_TILES; t++) {
            const __nv_bfloat16* g = srcs[t] + kk;
            const uint32_t tb = st + t * TILE_B;
            #pragma unroll
            for (int i = 0; i < 4; i++) {
                const int e = tid + 256 * i;       // 0..1023
                const int r = e >> 3;
                const int cch = e & 7;
                CP_ASYNC16(tb + r * SM_STRB + cch * 16,
                           (const void*)(g + (size_t)r * K + cch * 8));
            }
        }
        CP_COMMIT();
    };

    float acc[2][8][4];
    #pragma unroll
    for (int mi = 0; mi < 2; mi++)
        #pragma unroll
        for (int ni = 0; ni < 8; ni++)
            #pragma unroll
            for (int q = 0; q < 4; q++) acc[mi][ni][q] = 0.f;

    const int a_row_off = (lid & 7) + ((lid >> 3) & 1) * 8;
    const int a_k_off   = ((lid >> 4) & 1) * 8;
    const int b_n_off   = (lid & 7) + ((lid >> 4) & 1) * 8;
    const int b_k_off   = ((lid >> 3) & 1) * 8;

    load_chunk(0);

    for (int c = 0; c < segN; c++) {
        if (c + 1 < segN) load_chunk(c + 1);
        if (c + 1 < segN) { CP_WAIT(1); } else { CP_WAIT(0); }
        __syncthreads();

        const uint32_t st  = sbase + (c & 1) * STAGE_B;
        const uint32_t sAh = st;
        const uint32_t sAl = st + TILE_B;                       // SPLIT3 only
        const uint32_t sBh = st + (SPLIT3 ? 2 : 1) * TILE_B;
        const uint32_t sBl = st + 3 * TILE_B;                   // SPLIT3 only

        #pragma unroll
        for (int k16 = 0; k16 < 64; k16 += 16) {
            uint32_t ah[2][4], al[2][4];
            #pragma unroll
            for (int mi = 0; mi < 2; mi++) {
                const uint32_t roff =
                    (warp_m * 32 + mi * 16 + a_row_off) * SM_STRB + (k16 + a_k_off) * 2;
                LDMATRIX_X4(ah[mi][0], ah[mi][1], ah[mi][2], ah[mi][3], sAh + roff);
                if (SPLIT3)
                    LDMATRIX_X4(al[mi][0], al[mi][1], al[mi][2], al[mi][3], sAl + roff);
            }
            uint32_t bh[8][2], bl[8][2];
            #pragma unroll
            for (int np = 0; np < 4; np++) {
                const uint32_t roff =
                    (warp_n * 64 + np * 16 + b_n_off) * SM_STRB + (k16 + b_k_off) * 2;
                uint32_t r0, r1, r2, r3;
                LDMATRIX_X4(r0, r1, r2, r3, sBh + roff);
                bh[2 * np][0] = r0; bh[2 * np][1] = r1;
                bh[2 * np + 1][0] = r2; bh[2 * np + 1][1] = r3;
                if (SPLIT3) {
                    LDMATRIX_X4(r0, r1, r2, r3, sBl + roff);
                    bl[2 * np][0] = r0; bl[2 * np][1] = r1;
                    bl[2 * np + 1][0] = r2; bl[2 * np + 1][1] = r3;
                }
            }
            #pragma unroll
            for (int mi = 0; mi < 2; mi++)
                #pragma unroll
                for (int ni = 0; ni < 8; ni++) {
                    if (SPLIT3) {
                        MMA_BF16(acc[mi][ni][0], acc[mi][ni][1],
                                 acc[mi][ni][2], acc[mi][ni][3],
                                 ah[mi][0], ah[mi][1], ah[mi][2], ah[mi][3],
                                 bh[ni][0], bh[ni][1]);
                        MMA_BF16(acc[mi][ni][0], acc[mi][ni][1],
                                 acc[mi][ni][2], acc[mi][ni][3],
                                 ah[mi][0], ah[mi][1], ah[mi][2], ah[mi][3],
                                 bl[ni][0], bl[ni][1]);
                        MMA_BF16(acc[mi][ni][0], acc[mi][ni][1],
                                 acc[mi][ni][2], acc[mi][ni][3],
                                 al[mi][0], al[mi][1], al[mi][2], al[mi][3],
                                 bh[ni][0], bh[ni][1]);
                    } else {
                        MMA_FP16(acc[mi][ni][0], acc[mi][ni][1],
                                 acc[mi][ni][2], acc[mi][ni][3],
                                 ah[mi][0], ah[mi][1], ah[mi][2], ah[mi][3],
                                 bh[ni][0], bh[ni][1]);
                    }
                }
        }
        __syncthreads();
    }

    const int lr = lid >> 2;
    const int lc = (lid & 3) * 2;
    #pragma unroll
    for (int mi = 0; mi < 2; mi++) {
        #pragma unroll
        for (int ni = 0; ni < 8; ni++) {
            const int col = bn + warp_n * 64 + ni * 8 + lc;
            #pragma unroll
            for (int half = 0; half < 2; half++) {
                const int row = bm + warp_m * 32 + mi * 16 + lr + half * 8;
                const size_t off = (size_t)row * N + col;
                float v0 = acc[mi][ni][2 * half];
                float v1 = acc[mi][ni][2 * half + 1];
                if (MODE == 4) {
                    __nv_bfloat16 h0 = bf_hi(v0), h1 = bf_hi(v1);
                    *(uint32_t*)(Oh + off) = pack2(h0, h1);
                    *(uint32_t*)(Ol + off) = pack2(bf_lo(v0, h0), bf_lo(v1, h1));
                } else if (MODE == 5) {
                    v0 = fmaxf(v0 + bias[col], 0.f);
                    v1 = fmaxf(v1 + bias[col + 1], 0.f);
                    *(uint32_t*)((__half*)Oh + off) =
                        pack2h(__float2half(v0), __float2half(v1));
                } else {
                    if (MODE == 3) { v0 += bias[col]; v1 += bias[col + 1]; }
                    const float2 rr = *(const float2*)(res + off);
                    v0 += rr.x; v1 += rr.y;
                    *(float2*)(Cf + off) = make_float2(v0, v1);
                }
            }
        }
    }
}

// ---------------------------------------------------------------------------
// Tensor-core causal flash attention, split-3 bf16 (as round 6)
// ---------------------------------------------------------------------------
#define ATT_STR  72
#define ATT_STRB (ATT_STR * 2)
#define ATT_QT_B (128 * ATT_STRB)          // 18432
#define ATT_KV_B (64 * ATT_STRB)           // 9216
#define ATT_ST_B (4 * ATT_KV_B)            // 36864

__global__ void __launch_bounds__(256) attention_mma_kernel(
    const __nv_bfloat16* __restrict__ QKVh, const __nv_bfloat16* __restrict__ QKVl,
    __nv_bfloat16* __restrict__ Oh, __nv_bfloat16* __restrict__ Ol)
{
    const uint32_t sbase = smem_u32(smem_raw);
    const uint32_t sQh = sbase;
    const uint32_t sQl = sbase + ATT_QT_B;

    const int qt = blockIdx.x;
    const int bh = blockIdx.y;
    const int b  = bh >> 4;
    const int h  = bh & 15;
    const int q0 = qt * 128;
    const size_t rowbase = (size_t)b * SS;

    const int tid = threadIdx.x;
    const int w   = tid >> 5;
    const int lid = tid & 31;
    const int lr  = lid >> 2;
    const int lq  = lid & 3;

    const int a_row_off = (lid & 7) + ((lid >> 3) & 1) * 8;
    const int a_k_off   = ((lid >> 4) & 1) * 8;
    const int b_n_off   = (lid & 7) + ((lid >> 4) & 1) * 8;
    const int b_k_off   = ((lid >> 3) & 1) * 8;
    const int v_row_off = (lid & 7) + ((lid >> 3) & 1) * 8;
    const int v_col_off = ((lid >> 4) & 1) * 8;

    {
        const size_t qcol = (size_t)h * DK;
        #pragma unroll
        for (int i = 0; i < 4; i++) {
            const int e = tid + 256 * i;
            const int r = e >> 3;
            const int c = e & 7;
            const size_t g = (rowbase + q0 + r) * QKVN + qcol + c * 8;
            const uint32_t sm = r * ATT_STRB + c * 16;
            uint4 vh = *(const uint4*)(QKVh + g);
            uint4 vl = *(const uint4*)(QKVl + g);
            __nv_bfloat16* ph = (__nv_bfloat16*)&vh;
            __nv_bfloat16* pl = (__nv_bfloat16*)&vl;
            #pragma unroll
            for (int j = 0; j < 8; j++) {
                ph[j] = __float2bfloat16(__bfloat162float(ph[j]) * 0.125f);
                pl[j] = __float2bfloat16(__bfloat162float(pl[j]) * 0.125f);
            }
            *(uint4*)(smem_raw + (sQh - sbase) + sm) = vh;
            *(uint4*)(smem_raw + (sQl - sbase) + sm) = vl;
        }
    }

    auto kv_load = [&](int kt) {
        const uint32_t st = sbase + 2 * ATT_QT_B + (kt & 1) * ATT_ST_B;
        const size_t kcol = 1024 + (size_t)h * DK;
        const size_t vcol = 2048 + (size_t)h * DK;
        #pragma unroll
        for (int i = 0; i < 2; i++) {
            const int e = tid + 256 * i;
            const int r = e >> 3;
            const int c = e & 7;
            const size_t grow = (rowbase + kt * 64 + r) * QKVN;
            const uint32_t sm = r * ATT_STRB + c * 16;
            CP_ASYNC16(st + 0 * ATT_KV_B + sm, (const void*)(QKVh + grow + kcol + c * 8));
            CP_ASYNC16(st + 1 * ATT_KV_B + sm, (const void*)(QKVl + grow + kcol + c * 8));
            CP_ASYNC16(st + 2 * ATT_KV_B + sm, (const void*)(QKVh + grow + vcol + c * 8));
            CP_ASYNC16(st + 3 * ATT_KV_B + sm, (const void*)(QKVl + grow + vcol + c * 8));
        }
        CP_COMMIT();
    };

    float m0 = -1e30f, m1 = -1e30f, l0 = 0.f, l1 = 0.f;
    float o[8][4];
    #pragma unroll
    for (int ni = 0; ni < 8; ni++)
        #pragma unroll
        for (int q = 0; q < 4; q++) o[ni][q] = 0.f;

    const int NT = 2 * qt + 2;
    kv_load(0);

    for (int kt = 0; kt < NT; kt++) {
        if (kt + 1 < NT) kv_load(kt + 1);
        if (kt + 1 < NT) { CP_WAIT(1); } else { CP_WAIT(0); }
        __syncthreads();

        const int wrow_min = q0 + w * 16;
        const bool active  = (64 * kt <= wrow_min + 15);
        if (active) {
            const uint32_t st  = sbase + 2 * ATT_QT_B + (kt & 1) * ATT_ST_B;
            const uint32_t sKh = st;
            const uint32_t sKl = st + ATT_KV_B;
            const uint32_t sVh = st + 2 * ATT_KV_B;
            const uint32_t sVl = st + 3 * ATT_KV_B;

            float s[8][4];
            #pragma unroll
            for (int ni = 0; ni < 8; ni++)
                #pragma unroll
                for (int q = 0; q < 4; q++) s[ni][q] = 0.f;

            const uint32_t QT[3] = { sQh, sQh, sQl };
            const uint32_t KT[3] = { sKh, sKl, sKh };
            #pragma unroll
            for (int p = 0; p < 3; p++) {
                #pragma unroll
                for (int k16 = 0; k16 < 64; k16 += 16) {
                    uint32_t a0, a1, a2, a3;
                    LDMATRIX_X4(a0, a1, a2, a3,
                        QT[p] + (w * 16 + a_row_off) * ATT_STRB + (k16 + a_k_off) * 2);
                    uint32_t bb[8][2];
                    #pragma unroll
                    for (int np = 0; np < 4; np++) {
                        uint32_t r0, r1, r2, r3;
                        LDMATRIX_X4(r0, r1, r2, r3,
                            KT[p] + (np * 16 + b_n_off) * ATT_STRB + (k16 + b_k_off) * 2);
                        bb[2 * np][0] = r0; bb[2 * np][1] = r1;
                        bb[2 * np + 1][0] = r2; bb[2 * np + 1][1] = r3;
                    }
                    #pragma unroll
                    for (int ni = 0; ni < 8; ni++)
                        MMA_BF16(s[ni][0], s[ni][1], s[ni][2], s[ni][3],
                                 a0, a1, a2, a3, bb[ni][0], bb[ni][1]);
                }
            }

            if (64 * kt + 63 > wrow_min) {
                const int r0g = wrow_min + lr;
                const int r1g = r0g + 8;
                #pragma unroll
                for (int ni = 0; ni < 8; ni++) {
                    const int c0 = 64 * kt + ni * 8 + lq * 2;
                    if (c0 > r0g)     s[ni][0] = -1e30f;
                    if (c0 + 1 > r0g) s[ni][1] = -1e30f;
                    if (c0 > r1g)     s[ni][2] = -1e30f;
                    if (c0 + 1 > r1g) s[ni][3] = -1e30f;
                }
            }

            float mt0 = -1e30f, mt1 = -1e30f;
            #pragma unroll
            for (int ni = 0; ni < 8; ni++) {
                mt0 = fmaxf(mt0, fmaxf(s[ni][0], s[ni][1]));
                mt1 = fmaxf(mt1, fmaxf(s[ni][2], s[ni][3]));
            }
            mt0 = fmaxf(mt0, __shfl_xor_sync(0xffffffffu, mt0, 1));
            mt0 = fmaxf(mt0, __shfl_xor_sync(0xffffffffu, mt0, 2));
            mt1 = fmaxf(mt1, __shfl_xor_sync(0xffffffffu, mt1, 1));
            mt1 = fmaxf(mt1, __shfl_xor_sync(0xffffffffu, mt1, 2));
            const float mn0 = fmaxf(m0, mt0), mn1 = fmaxf(m1, mt1);
            const float cr0 = __expf(m0 - mn0), cr1 = __expf(m1 - mn1);
            float rs0 = 0.f, rs1 = 0.f;
            #pragma unroll
            for (int ni = 0; ni < 8; ni++) {
                s[ni][0] = __expf(s[ni][0] - mn0); rs0 += s[ni][0];
                s[ni][1] = __expf(s[ni][1] - mn0); rs0 += s[ni][1];
                s[ni][2] = __expf(s[ni][2] - mn1); rs1 += s[ni][2];
                s[ni][3] = __expf(s[ni][3] - mn1); rs1 += s[ni][3];
            }
            rs0 += __shfl_xor_sync(0xffffffffu, rs0, 1);
            rs0 += __shfl_xor_sync(0xffffffffu, rs0, 2);
            rs1 += __shfl_xor_sync(0xffffffffu, rs1, 1);
            rs1 += __shfl_xor_sync(0xffffffffu, rs1, 2);
            l0 = l0 * cr0 + rs0;  l1 = l1 * cr1 + rs1;
            m0 = mn0;  m1 = mn1;
            #pragma unroll
            for (int ni = 0; ni < 8; ni++) {
                o[ni][0] *= cr0; o[ni][1] *= cr0;
                o[ni][2] *= cr1; o[ni][3] *= cr1;
            }

            #pragma unroll
            for (int j = 0; j < 4; j++) {
                const int t0 = 2 * j, t1 = 2 * j + 1;
                __nv_bfloat16 h00 = bf_hi(s[t0][0]), h01 = bf_hi(s[t0][1]);
                __nv_bfloat16 h02 = bf_hi(s[t0][2]), h03 = bf_hi(s[t0][3]);
                __nv_bfloat16 h10 = bf_hi(s[t1][0]), h11 = bf_hi(s[t1][1]);
                __nv_bfloat16 h12 = bf_hi(s[t1][2]), h13 = bf_hi(s[t1][3]);
                const uint32_t ah0 = pack2(h00, h01);
                const uint32_t ah1 = pack2(h02, h03);
                const uint32_t ah2 = pack2(h10, h11);
                const uint32_t ah3 = pack2(h12, h13);
                const uint32_t al0 = pack2(bf_lo(s[t0][0], h00), bf_lo(s[t0][1], h01));
                const uint32_t al1 = pack2(bf_lo(s[t0][2], h02), bf_lo(s[t0][3], h03));
                const uint32_t al2 = pack2(bf_lo(s[t1][0], h10), bf_lo(s[t1][1], h11));
                const uint32_t al3 = pack2(bf_lo(s[t1][2], h12), bf_lo(s[t1][3], h13));

                #pragma unroll
                for (int np = 0; np < 4; np++) {
                    uint32_t bh0, bh1, bh2, bh3, bl0, bl1, bl2, bl3;
                    const uint32_t vaddr =
                        (j * 16 + v_row_off) * ATT_STRB + (np * 16 + v_col_off) * 2;
                    LDMATRIX_X4_T(bh0, bh1, bh2, bh3, sVh + vaddr);
                    LDMATRIX_X4_T(bl0, bl1, bl2, bl3, sVl + vaddr);
                    MMA_BF16(o[2*np][0], o[2*np][1], o[2*np][2], o[2*np][3],
                             ah0, ah1, ah2, ah3, bh0, bh1);
                    MMA_BF16(o[2*np+1][0], o[2*np+1][1], o[2*np+1][2], o[2*np+1][3],
                             ah0, ah1, ah2, ah3, bh2, bh3);
                    MMA_BF16(o[2*np][0], o[2*np][1], o[2*np][2], o[2*np][3],
                             ah0, ah1, ah2, ah3, bl0, bl1);
                    MMA_BF16(o[2*np+1][0], o[2*np+1][1], o[2*np+1][2], o[2*np+1][3],
                             ah0, ah1, ah2, ah3, bl2, bl3);
                    MMA_BF16(o[2*np][0], o[2*np][1], o[2*np][2], o[2*np][3],
                             al0, al1, al2, al3, bh0, bh1);
                    MMA_BF16(o[2*np+1][0], o[2*np+1][1], o[2*np+1][2], o[2*np+1][3],
                             al0, al1, al2, al3, bh2, bh3);
                }
            }
        }
        __syncthreads();
    }

    const float inv0 = 1.f / l0, inv1 = 1.f / l1;
    #pragma unroll
    for (int ni = 0; ni < 8; ni++) {
        const int col = h * DK + ni * 8 + lq * 2;
        {
            const size_t off = (rowbase + q0 + w * 16 + lr) * DMODEL + col;
            const float f0 = o[ni][0] * inv0, f1 = o[ni][1] * inv0;
            __nv_bfloat16 h0 = bf_hi(f0), h1 = bf_hi(f1);
            *(uint32_t*)(Oh + off) = pack2(h0, h1);
            *(uint32_t*)(Ol + off) = pack2(bf_lo(f0, h0), bf_lo(f1, h1));
        }
        {
            const size_t off = (rowbase + q0 + w * 16 + lr + 8) * DMODEL + col;
            const float f0 = o[ni][2] * inv1, f1 = o[ni][3] * inv1;
            __nv_bfloat16 h0 = bf_hi(f0), h1 = bf_hi(f1);
            *(uint32_t*)(Oh + off) = pack2(h0, h1);
            *(uint32_t*)(Ol + off) = pack2(bf_lo(f0, h0), bf_lo(f1, h1));
        }
    }
}

// ---------------------------------------------------------------------------
// Launch
// ---------------------------------------------------------------------------
extern "C" void kernel_launch(void* const* d_in, const int* in_sizes, int n_in,
                              void* d_out, int out_size)
{
    const float* x   = (const float*)d_in[0];
    const float* Wq  = (const float*)d_in[1];
    const float* Wk  = (const float*)d_in[2];
    const float* Wv  = (const float*)d_in[3];
    const float* Wo  = (const float*)d_in[4];
    const float* W1  = (const float*)d_in[5];
    const float* b1  = (const float*)d_in[6];
    const float* W2  = (const float*)d_in[7];
    const float* b2  = (const float*)d_in[8];
    const float* g1  = (const float*)d_in[9];
    const float* be1 = (const float*)d_in[10];
    const float* g2  = (const float*)d_in[11];
    const float* be2 = (const float*)d_in[12];
    float* out = (float*)d_out;

    float *x2;
    __nv_bfloat16 *ah, *al, *qkvh, *qkvl, *wh, *wl;
    __half *ffh;
    cudaGetSymbolAddress((void**)&x2,   g_x2);
    cudaGetSymbolAddress((void**)&ah,   g_a_hi);
    cudaGetSymbolAddress((void**)&al,   g_a_lo);
    cudaGetSymbolAddress((void**)&qkvh, g_qkv_hi);
    cudaGetSymbolAddress((void**)&qkvl, g_qkv_lo);
    cudaGetSymbolAddress((void**)&ffh,  g_ffh);
    cudaGetSymbolAddress((void**)&wh,   g_w_hi);
    cudaGetSymbolAddress((void**)&wl,   g_w_lo);

    const int GEMM3_SMEM = 2 * 4 * TILE_B;   // 147456 (split-3)
    const int GEMM1_SMEM = 2 * 2 * TILE_B;   // 73728  (fp16 single)
    cudaFuncSetAttribute(gemm_mma_kernel<1, true>,  cudaFuncAttributeMaxDynamicSharedMemorySize, GEMM3_SMEM);
    cudaFuncSetAttribute(gemm_mma_kernel<4, true>,  cudaFuncAttributeMaxDynamicSharedMemorySize, GEMM3_SMEM);
    cudaFuncSetAttribute(gemm_mma_kernel<5, false>, cudaFuncAttributeMaxDynamicSharedMemorySize, GEMM1_SMEM);
    cudaFuncSetAttribute(gemm_mma_kernel<3, false>, cudaFuncAttributeMaxDynamicSharedMemorySize, GEMM1_SMEM);
    const int ATTN_SMEM = 2 * ATT_QT_B + 2 * ATT_ST_B;   // 110592
    cudaFuncSetAttribute(attention_mma_kernel, cudaFuncAttributeMaxDynamicSharedMemorySize, ATTN_SMEM);

    // 0) weight transpose: Wq..Wo bf16 hi/lo; W1/W2 fp16 single
    {
        dim3 tb(32, 8);
        transpose_split_kernel<0><<<dim3(32,  32), tb>>>(Wq, wh + 0 * MEG, wl + 0 * MEG, 1024, 1024);
        transpose_split_kernel<0><<<dim3(32,  32), tb>>>(Wk, wh + 1 * MEG, wl + 1 * MEG, 1024, 1024);
        transpose_split_kernel<0><<<dim3(32,  32), tb>>>(Wv, wh + 2 * MEG, wl + 2 * MEG, 1024, 1024);
        transpose_split_kernel<0><<<dim3(32,  32), tb>>>(Wo, wh + 3 * MEG, wl + 3 * MEG, 1024, 1024);
        transpose_split_kernel<1><<<dim3(128, 32), tb>>>(W1, wh + 4 * MEG, nullptr, 1024, 4096);
        transpose_split_kernel<1><<<dim3(32, 128), tb>>>(W2, wh + 8 * MEG, nullptr, 4096, 1024);
    }

    // 1) LN1 -> bf16 split
    layernorm_split_kernel<0><<<MROWS, 256>>>(x, g1, be1, ah, al);

    // 2) fused QKV projection (bf16 split-3) -> bf16 hi/lo [row][3072]
    {
        dim3 grid(QKVN / 128, MROWS / 128);
        gemm_mma_kernel<4, true><<<grid, 256, GEMM3_SMEM>>>(ah, al, wh, wl,
            nullptr, nullptr, nullptr, qkvh, qkvl, MROWS, QKVN, DMODEL);
    }

    // 3) tensor-core causal attention -> ah/al
    {
        dim3 grid(SS / 128, BB * NHEADS);
        attention_mma_kernel<<<grid, 256, ATTN_SMEM>>>(qkvh, qkvl, ah, al);
    }

    // 4) output projection + residual(x) -> x2 (f32), bf16 split-3
    {
        dim3 grid(DMODEL / 128, MROWS / 128);
        gemm_mma_kernel<1, true><<<grid, 256, GEMM3_SMEM>>>(ah, al, wh + 3 * MEG, wl + 3 * MEG,
            nullptr, x, x2, nullptr, nullptr, MROWS, DMODEL, DMODEL);
    }

    // 5) LN2 -> fp16 single (into ah)
    layernorm_split_kernel<1><<<MROWS, 256>>>(x2, g2, be2, ah, nullptr);

    // 6) FFN1 (fp16 single): relu(h2 @ W1 + b1) -> fp16 (ffh)
    {
        dim3 grid(DFF / 128, MROWS / 128);
        gemm_mma_kernel<5, false><<<grid, 256, GEMM1_SMEM>>>(
            ah, nullptr, wh + 4 * MEG, nullptr,
            b1, nullptr, nullptr, (__nv_bfloat16*)ffh, nullptr, MROWS, DFF, DMODEL);
    }

    // 7) FFN2 (fp16 single): ff @ W2 + b2 + x2 -> out
    {
        dim3 grid(DMODEL / 128, MROWS / 128);
        gemm_mma_kernel<3, false><<<grid, 256, GEMM1_SMEM>>>(
            (const __nv_bfloat16*)ffh, nullptr, wh + 8 * MEG, nullptr,
            b2, x2, out, nullptr, nullptr, MROWS, DMODEL, DFF);
    }
}

// round 8
// speedup vs baseline: 7.0345x; 1.6341x over previous
#include <cuda_runtime.h>
#include <cuda_fp16.h>
#include <cstdint>
#include <math.h>

// ---------------------------------------------------------------------------
// Problem dims
// ---------------------------------------------------------------------------
#define BB      16
#define SS      512
#define DMODEL  1024
#define NHEADS  16
#define DK      64
#define DFF     4096
#define MROWS   (BB * SS)          // 8192
#define MEG     (1024 * 1024)
#define QKVN    3072

// ---------------------------------------------------------------------------
// Scratch (device globals) — all activations fp16
// ---------------------------------------------------------------------------
__device__ float  g_x2 [MROWS * DMODEL];
__device__ __half g_ln [MROWS * DMODEL];     // ln1 out, then ln2 out
__device__ __half g_att[MROWS * DMODEL];     // attention out
__device__ __half g_qkv[MROWS * QKVN];       // fused q|k|v
__device__ __half g_ff [MROWS * DFF];        // ffn intermediate
__device__ __half g_w  [12 * MEG];           // transposed fp16 weights
// offsets: Wq=0, Wk=1M, Wv=2M (contiguous [3072][1024]), Wo=3M, W1t=4M, W2t=8M

extern __shared__ char smem_raw[];

// ---------------------------------------------------------------------------
// PTX helpers
// ---------------------------------------------------------------------------
__device__ __forceinline__ uint32_t smem_u32(const void* p) {
    uint32_t a;
    asm("{ .reg .u64 t; cvta.to.shared.u64 t, %1; cvt.u32.u64 %0, t; }"
        : "=r"(a) : "l"(p));
    return a;
}
#define CP_ASYNC16(dst, src) \
    asm volatile("cp.async.cg.shared.global [%0], [%1], 16;" :: "r"(dst), "l"(src))
#define CP_COMMIT() asm volatile("cp.async.commit_group;" ::: "memory")
#define CP_WAIT(n)  asm volatile("cp.async.wait_group %0;" :: "n"(n) : "memory")

#define LDMATRIX_X4(r0, r1, r2, r3, addr) \
    asm volatile("ldmatrix.sync.aligned.m8n8.x4.shared.b16 {%0,%1,%2,%3}, [%4];" \
                 : "=r"(r0), "=r"(r1), "=r"(r2), "=r"(r3) : "r"(addr))
#define LDMATRIX_X4_T(r0, r1, r2, r3, addr) \
    asm volatile("ldmatrix.sync.aligned.m8n8.x4.trans.shared.b16 {%0,%1,%2,%3}, [%4];" \
                 : "=r"(r0), "=r"(r1), "=r"(r2), "=r"(r3) : "r"(addr))

#define MMA_FP16(c0, c1, c2, c3, a0, a1, a2, a3, b0, b1) \
    asm volatile("mma.sync.aligned.m16n8k16.row.col.f32.f16.f16.f32 " \
                 "{%0,%1,%2,%3}, {%4,%5,%6,%7}, {%8,%9}, {%0,%1,%2,%3};" \
                 : "+f"(c0), "+f"(c1), "+f"(c2), "+f"(c3) \
                 : "r"(a0), "r"(a1), "r"(a2), "r"(a3), "r"(b0), "r"(b1))

__device__ __forceinline__ uint32_t pack2h(__half x, __half y) {
    return (uint32_t)__half_as_ushort(x) |
           ((uint32_t)__half_as_ushort(y) << 16);
}

// ---------------------------------------------------------------------------
// Weight transpose -> fp16:  W[K][N] fp32  ->  out[N][K] fp16
// ---------------------------------------------------------------------------
__global__ void __launch_bounds__(256) transpose_fp16_kernel(
    const float* __restrict__ W, __half* __restrict__ o, int K, int N)
{
    __shared__ float t[32][33];
    const int tx = threadIdx.x, ty = threadIdx.y;
    const int n0 = blockIdx.x * 32;
    const int k0 = blockIdx.y * 32;
    #pragma unroll
    for (int j = 0; j < 32; j += 8)
        t[ty + j][tx] = W[(size_t)(k0 + ty + j) * N + n0 + tx];
    __syncthreads();
    #pragma unroll
    for (int j = 0; j < 32; j += 8)
        o[(size_t)(n0 + ty + j) * K + k0 + tx] = __float2half(t[tx][ty + j]);
}

// ---------------------------------------------------------------------------
// LayerNorm -> fp16
// ---------------------------------------------------------------------------
__global__ void __launch_bounds__(256) layernorm_fp16_kernel(
    const float* __restrict__ x, const float* __restrict__ g,
    const float* __restrict__ be, __half* __restrict__ o)
{
    const int row = blockIdx.x;
    const int tid = threadIdx.x;
    const float4 v = *(const float4*)(x + (size_t)row * DMODEL + tid * 4);

    float s1 = v.x + v.y + v.z + v.w;
    float s2 = v.x * v.x + v.y * v.y + v.z * v.z + v.w * v.w;
    #pragma unroll
    for (int off = 16; off > 0; off >>= 1) {
        s1 += __shfl_xor_sync(0xffffffffu, s1, off);
        s2 += __shfl_xor_sync(0xffffffffu, s2, off);
    }
    __shared__ float sm1[8], sm2[8];
    const int w = tid >> 5, l = tid & 31;
    if (l == 0) { sm1[w] = s1; sm2[w] = s2; }
    __syncthreads();
    if (w == 0) {
        s1 = (l < 8) ? sm1[l] : 0.f;
        s2 = (l < 8) ? sm2[l] : 0.f;
        #pragma unroll
        for (int off = 4; off > 0; off >>= 1) {
            s1 += __shfl_xor_sync(0xffffffffu, s1, off);
            s2 += __shfl_xor_sync(0xffffffffu, s2, off);
        }
        if (l == 0) { sm1[0] = s1; sm2[0] = s2; }
    }
    __syncthreads();

    const float mu  = sm1[0] * (1.f / DMODEL);
    const float var = sm2[0] * (1.f / DMODEL) - mu * mu;
    const float inv = rsqrtf(var + 1e-5f);

    const float4 gv = *(const float4*)(g  + tid * 4);
    const float4 bv = *(const float4*)(be + tid * 4);
    __align__(8) __half h4[4];
    h4[0] = __float2half((v.x - mu) * inv * gv.x + bv.x);
    h4[1] = __float2half((v.y - mu) * inv * gv.y + bv.y);
    h4[2] = __float2half((v.z - mu) * inv * gv.z + bv.z);
    h4[3] = __float2half((v.w - mu) * inv * gv.w + bv.w);
    *(uint2*)(o + (size_t)row * DMODEL + tid * 4) = *(uint2*)h4;
}

// ---------------------------------------------------------------------------
// fp16 single-pass mma.sync GEMM: C[M,N] = A[M,K] @ B^T[N,K]
// CTA tile 128x128, BK=64, 2-stage cp.async (73728 B smem -> 2 CTA/SM)
// MODE: 0 = fp16 plain | 1 = f32 +res | 2 = fp16 relu(+bias) | 3 = f32 +bias +res
// ---------------------------------------------------------------------------
#define SM_STRIDE 72
#define SM_STRB   (SM_STRIDE * 2)
#define TILE_B    (128 * SM_STRB)          // 18432
#define STAGE_B   (2 * TILE_B)             // 36864

template<int MODE>
__global__ void __launch_bounds__(256) gemm_fp16_kernel(
    const __half* __restrict__ A, const __half* __restrict__ B,
    const float* __restrict__ bias, const float* __restrict__ res,
    float* __restrict__ Cf, __half* __restrict__ Oh, int M, int N, int K)
{
    const uint32_t sbase = smem_u32(smem_raw);
    const int tid = threadIdx.x;
    const int wid = tid >> 5, lid = tid & 31;
    const int warp_m = wid & 3;
    const int warp_n = wid >> 2;
    const int bm = blockIdx.y * 128;
    const int bn = blockIdx.x * 128;

    const int segN = K >> 6;
    const __half* Ag0 = A + (size_t)bm * K;
    const __half* Bg0 = B + (size_t)bn * K;

    auto load_chunk = [&](int c) {
        const uint32_t st = sbase + (c & 1) * STAGE_B;
        const int kk = c << 6;
        const __half* Ag = Ag0 + kk;
        const __half* Bg = Bg0 + kk;
        #pragma unroll
        for (int i = 0; i < 4; i++) {
            const int e = tid + 256 * i;       // 0..1023
            const int r = e >> 3;
            const int cch = e & 7;
            CP_ASYNC16(st + r * SM_STRB + cch * 16,
                       (const void*)(Ag + (size_t)r * K + cch * 8));
            CP_ASYNC16(st + TILE_B + r * SM_STRB + cch * 16,
                       (const void*)(Bg + (size_t)r * K + cch * 8));
        }
        CP_COMMIT();
    };

    float acc[2][8][4];
    #pragma unroll
    for (int mi = 0; mi < 2; mi++)
        #pragma unroll
        for (int ni = 0; ni < 8; ni++)
            #pragma unroll
            for (int q = 0; q < 4; q++) acc[mi][ni][q] = 0.f;

    const int a_row_off = (lid & 7) + ((lid >> 3) & 1) * 8;
    const int a_k_off   = ((lid >> 4) & 1) * 8;
    const int b_n_off   = (lid & 7) + ((lid >> 4) & 1) * 8;
    const int b_k_off   = ((lid >> 3) & 1) * 8;

    load_chunk(0);

    for (int c = 0; c < segN; c++) {
        if (c + 1 < segN) load_chunk(c + 1);
        if (c + 1 < segN) { CP_WAIT(1); } else { CP_WAIT(0); }
        __syncthreads();

        const uint32_t sA = sbase + (c & 1) * STAGE_B;
        const uint32_t sB = sA + TILE_B;

        #pragma unroll
        for (int k16 = 0; k16 < 64; k16 += 16) {
            uint32_t a[2][4];
            #pragma unroll
            for (int mi = 0; mi < 2; mi++) {
                const uint32_t roff =
                    (warp_m * 32 + mi * 16 + a_row_off) * SM_STRB + (k16 + a_k_off) * 2;
                LDMATRIX_X4(a[mi][0], a[mi][1], a[mi][2], a[mi][3], sA + roff);
            }
            uint32_t b[8][2];
            #pragma unroll
            for (int np = 0; np < 4; np++) {
                const uint32_t roff =
                    (warp_n * 64 + np * 16 + b_n_off) * SM_STRB + (k16 + b_k_off) * 2;
                uint32_t r0, r1, r2, r3;
                LDMATRIX_X4(r0, r1, r2, r3, sB + roff);
                b[2 * np][0] = r0; b[2 * np][1] = r1;
                b[2 * np + 1][0] = r2; b[2 * np + 1][1] = r3;
            }
            #pragma unroll
            for (int mi = 0; mi < 2; mi++)
                #pragma unroll
                for (int ni = 0; ni < 8; ni++)
                    MMA_FP16(acc[mi][ni][0], acc[mi][ni][1],
                             acc[mi][ni][2], acc[mi][ni][3],
                             a[mi][0], a[mi][1], a[mi][2], a[mi][3],
                             b[ni][0], b[ni][1]);
        }
        __syncthreads();
    }

    const int lr = lid >> 2;
    const int lc = (lid & 3) * 2;
    #pragma unroll
    for (int mi = 0; mi < 2; mi++) {
        #pragma unroll
        for (int ni = 0; ni < 8; ni++) {
            const int col = bn + warp_n * 64 + ni * 8 + lc;
            #pragma unroll
            for (int half = 0; half < 2; half++) {
                const int row = bm + warp_m * 32 + mi * 16 + lr + half * 8;
                const size_t off = (size_t)row * N + col;
                float v0 = acc[mi][ni][2 * half];
                float v1 = acc[mi][ni][2 * half + 1];
                if (MODE == 0) {
                    *(uint32_t*)(Oh + off) =
                        pack2h(__float2half(v0), __float2half(v1));
                } else if (MODE == 2) {
                    v0 = fmaxf(v0 + bias[col], 0.f);
                    v1 = fmaxf(v1 + bias[col + 1], 0.f);
                    *(uint32_t*)(Oh + off) =
                        pack2h(__float2half(v0), __float2half(v1));
                } else {
                    if (MODE == 3) { v0 += bias[col]; v1 += bias[col + 1]; }
                    const float2 rr = *(const float2*)(res + off);
                    v0 += rr.x; v1 += rr.y;
                    *(float2*)(Cf + off) = make_float2(v0, v1);
                }
            }
        }
    }
}

// ---------------------------------------------------------------------------
// fp16 tensor-core causal flash attention, 128 q-rows per block, 8 warps.
// K/V double-buffered cp.async; warps past the diagonal skip tiles.
// smem: Q[128][72] + 2 stages x {K,V}[64][72] = 55296 B -> 2 CTA/SM
// ---------------------------------------------------------------------------
#define ATT_STR  72
#define ATT_STRB (ATT_STR * 2)
#define ATT_Q_B  (128 * ATT_STRB)          // 18432
#define ATT_KV_B (64 * ATT_STRB)           // 9216
#define ATT_ST_B (2 * ATT_KV_B)            // 18432

__global__ void __launch_bounds__(256) attention_fp16_kernel(
    const __half* __restrict__ QKV, __half* __restrict__ O)
{
    const uint32_t sbase = smem_u32(smem_raw);
    const uint32_t sQ = sbase;

    const int qt = blockIdx.x;              // 0..3
    const int bh = blockIdx.y;
    const int b  = bh >> 4;
    const int h  = bh & 15;
    const int q0 = qt * 128;
    const size_t rowbase = (size_t)b * SS;

    const int tid = threadIdx.x;
    const int w   = tid >> 5;
    const int lid = tid & 31;
    const int lr  = lid >> 2;
    const int lq  = lid & 3;

    const int a_row_off = (lid & 7) + ((lid >> 3) & 1) * 8;
    const int a_k_off   = ((lid >> 4) & 1) * 8;
    const int b_n_off   = (lid & 7) + ((lid >> 4) & 1) * 8;
    const int b_k_off   = ((lid >> 3) & 1) * 8;
    const int v_row_off = (lid & 7) + ((lid >> 3) & 1) * 8;
    const int v_col_off = ((lid >> 4) & 1) * 8;

    // ---- load Q (scaled by 0.125, exact) ----
    {
        const size_t qcol = (size_t)h * DK;
        #pragma unroll
        for (int i = 0; i < 4; i++) {
            const int e = tid + 256 * i;       // 0..1023
            const int r = e >> 3;
            const int c = e & 7;
            const size_t g = (rowbase + q0 + r) * QKVN + qcol + c * 8;
            uint4 v = *(const uint4*)(QKV + g);
            __half* ph = (__half*)&v;
            #pragma unroll
            for (int j = 0; j < 8; j++)
                ph[j] = __float2half(__half2float(ph[j]) * 0.125f);
            *(uint4*)(smem_raw + r * ATT_STRB + c * 16) = v;
        }
    }

    auto kv_load = [&](int kt) {
        const uint32_t st = sbase + ATT_Q_B + (kt & 1) * ATT_ST_B;
        const size_t kcol = 1024 + (size_t)h * DK;
        const size_t vcol = 2048 + (size_t)h * DK;
        #pragma unroll
        for (int i = 0; i < 2; i++) {
            const int e = tid + 256 * i;       // 0..511
            const int r = e >> 3;
            const int c = e & 7;
            const size_t grow = (rowbase + kt * 64 + r) * QKVN;
            const uint32_t sm = r * ATT_STRB + c * 16;
            CP_ASYNC16(st + sm,            (const void*)(QKV + grow + kcol + c * 8));
            CP_ASYNC16(st + ATT_KV_B + sm, (const void*)(QKV + grow + vcol + c * 8));
        }
        CP_COMMIT();
    };

    float m0 = -1e30f, m1 = -1e30f, l0 = 0.f, l1 = 0.f;
    float o[8][4];
    #pragma unroll
    for (int ni = 0; ni < 8; ni++)
        #pragma unroll
        for (int q = 0; q < 4; q++) o[ni][q] = 0.f;

    const int NT = 2 * qt + 2;
    kv_load(0);

    for (int kt = 0; kt < NT; kt++) {
        if (kt + 1 < NT) kv_load(kt + 1);
        if (kt + 1 < NT) { CP_WAIT(1); } else { CP_WAIT(0); }
        __syncthreads();

        const int wrow_min = q0 + w * 16;
        if (64 * kt <= wrow_min + 15) {
            const uint32_t sK = sbase + ATT_Q_B + (kt & 1) * ATT_ST_B;
            const uint32_t sV = sK + ATT_KV_B;

            // ---- S = Q K^T ----
            float s[8][4];
            #pragma unroll
            for (int ni = 0; ni < 8; ni++)
                #pragma unroll
                for (int q = 0; q < 4; q++) s[ni][q] = 0.f;

            #pragma unroll
            for (int k16 = 0; k16 < 64; k16 += 16) {
                uint32_t a0, a1, a2, a3;
                LDMATRIX_X4(a0, a1, a2, a3,
                    sQ + (w * 16 + a_row_off) * ATT_STRB + (k16 + a_k_off) * 2);
                uint32_t bb[8][2];
                #pragma unroll
                for (int np = 0; np < 4; np++) {
                    uint32_t r0, r1, r2, r3;
                    LDMATRIX_X4(r0, r1, r2, r3,
                        sK + (np * 16 + b_n_off) * ATT_STRB + (k16 + b_k_off) * 2);
                    bb[2 * np][0] = r0; bb[2 * np][1] = r1;
                    bb[2 * np + 1][0] = r2; bb[2 * np + 1][1] = r3;
                }
                #pragma unroll
                for (int ni = 0; ni < 8; ni++)
                    MMA_FP16(s[ni][0], s[ni][1], s[ni][2], s[ni][3],
                             a0, a1, a2, a3, bb[ni][0], bb[ni][1]);
            }

            // ---- causal mask near diagonal ----
            if (64 * kt + 63 > wrow_min) {
                const int r0g = wrow_min + lr;
                const int r1g = r0g + 8;
                #pragma unroll
                for (int ni = 0; ni < 8; ni++) {
                    const int c0 = 64 * kt + ni * 8 + lq * 2;
                    if (c0 > r0g)     s[ni][0] = -1e30f;
                    if (c0 + 1 > r0g) s[ni][1] = -1e30f;
                    if (c0 > r1g)     s[ni][2] = -1e30f;
                    if (c0 + 1 > r1g) s[ni][3] = -1e30f;
                }
            }

            // ---- online softmax ----
            float mt0 = -1e30f, mt1 = -1e30f;
            #pragma unroll
            for (int ni = 0; ni < 8; ni++) {
                mt0 = fmaxf(mt0, fmaxf(s[ni][0], s[ni][1]));
                mt1 = fmaxf(mt1, fmaxf(s[ni][2], s[ni][3]));
            }
            mt0 = fmaxf(mt0, __shfl_xor_sync(0xffffffffu, mt0, 1));
            mt0 = fmaxf(mt0, __shfl_xor_sync(0xffffffffu, mt0, 2));
            mt1 = fmaxf(mt1, __shfl_xor_sync(0xffffffffu, mt1, 1));
            mt1 = fmaxf(mt1, __shfl_xor_sync(0xffffffffu, mt1, 2));
            const float mn0 = fmaxf(m0, mt0), mn1 = fmaxf(m1, mt1);
            const float cr0 = __expf(m0 - mn0), cr1 = __expf(m1 - mn1);
            float rs0 = 0.f, rs1 = 0.f;
            #pragma unroll
            for (int ni = 0; ni < 8; ni++) {
                s[ni][0] = __expf(s[ni][0] - mn0); rs0 += s[ni][0];
                s[ni][1] = __expf(s[ni][1] - mn0); rs0 += s[ni][1];
                s[ni][2] = __expf(s[ni][2] - mn1); rs1 += s[ni][2];
                s[ni][3] = __expf(s[ni][3] - mn1); rs1 += s[ni][3];
            }
            rs0 += __shfl_xor_sync(0xffffffffu, rs0, 1);
            rs0 += __shfl_xor_sync(0xffffffffu, rs0, 2);
            rs1 += __shfl_xor_sync(0xffffffffu, rs1, 1);
            rs1 += __shfl_xor_sync(0xffffffffu, rs1, 2);
            l0 = l0 * cr0 + rs0;  l1 = l1 * cr1 + rs1;
            m0 = mn0;  m1 = mn1;
            #pragma unroll
            for (int ni = 0; ni < 8; ni++) {
                o[ni][0] *= cr0; o[ni][1] *= cr0;
                o[ni][2] *= cr1; o[ni][3] *= cr1;
            }

            // ---- O += P V ----
            #pragma unroll
            for (int j = 0; j < 4; j++) {
                const int t0 = 2 * j, t1 = 2 * j + 1;
                const uint32_t a0 = pack2h(__float2half(s[t0][0]), __float2half(s[t0][1]));
                const uint32_t a1 = pack2h(__float2half(s[t0][2]), __float2half(s[t0][3]));
                const uint32_t a2 = pack2h(__float2half(s[t1][0]), __float2half(s[t1][1]));
                const uint32_t a3 = pack2h(__float2half(s[t1][2]), __float2half(s[t1][3]));
                #pragma unroll
                for (int np = 0; np < 4; np++) {
                    uint32_t b0, b1, b2, b3;
                    LDMATRIX_X4_T(b0, b1, b2, b3,
                        sV + (j * 16 + v_row_off) * ATT_STRB + (np * 16 + v_col_off) * 2);
                    MMA_FP16(o[2*np][0], o[2*np][1], o[2*np][2], o[2*np][3],
                             a0, a1, a2, a3, b0, b1);
                    MMA_FP16(o[2*np+1][0], o[2*np+1][1], o[2*np+1][2], o[2*np+1][3],
                             a0, a1, a2, a3, b2, b3);
                }
            }
        }
        __syncthreads();
    }

    // ---- finalize ----
    const float inv0 = 1.f / l0, inv1 = 1.f / l1;
    #pragma unroll
    for (int ni = 0; ni < 8; ni++) {
        const int col = h * DK + ni * 8 + lq * 2;
        {
            const size_t off = (rowbase + q0 + w * 16 + lr) * DMODEL + col;
            *(uint32_t*)(O + off) = pack2h(__float2half(o[ni][0] * inv0),
                                           __float2half(o[ni][1] * inv0));
        }
        {
            const size_t off = (rowbase + q0 + w * 16 + lr + 8) * DMODEL + col;
            *(uint32_t*)(O + off) = pack2h(__float2half(o[ni][2] * inv1),
                                           __float2half(o[ni][3] * inv1));
        }
    }
}

// ---------------------------------------------------------------------------
// Launch
// ---------------------------------------------------------------------------
extern "C" void kernel_launch(void* const* d_in, const int* in_sizes, int n_in,
                              void* d_out, int out_size)
{
    const float* x   = (const float*)d_in[0];
    const float* Wq  = (const float*)d_in[1];
    const float* Wk  = (const float*)d_in[2];
    const float* Wv  = (const float*)d_in[3];
    const float* Wo  = (const float*)d_in[4];
    const float* W1  = (const float*)d_in[5];
    const float* b1  = (const float*)d_in[6];
    const float* W2  = (const float*)d_in[7];
    const float* b2  = (const float*)d_in[8];
    const float* g1  = (const float*)d_in[9];
    const float* be1 = (const float*)d_in[10];
    const float* g2  = (const float*)d_in[11];
    const float* be2 = (const float*)d_in[12];
    float* out = (float*)d_out;

    float *x2;
    __half *ln, *att, *qkv, *ff, *wgt;
    cudaGetSymbolAddress((void**)&x2,  g_x2);
    cudaGetSymbolAddress((void**)&ln,  g_ln);
    cudaGetSymbolAddress((void**)&att, g_att);
    cudaGetSymbolAddress((void**)&qkv, g_qkv);
    cudaGetSymbolAddress((void**)&ff,  g_ff);
    cudaGetSymbolAddress((void**)&wgt, g_w);

    const int GEMM_SMEM = 2 * STAGE_B;                 // 73728
    cudaFuncSetAttribute(gemm_fp16_kernel<0>, cudaFuncAttributeMaxDynamicSharedMemorySize, GEMM_SMEM);
    cudaFuncSetAttribute(gemm_fp16_kernel<1>, cudaFuncAttributeMaxDynamicSharedMemorySize, GEMM_SMEM);
    cudaFuncSetAttribute(gemm_fp16_kernel<2>, cudaFuncAttributeMaxDynamicSharedMemorySize, GEMM_SMEM);
    cudaFuncSetAttribute(gemm_fp16_kernel<3>, cudaFuncAttributeMaxDynamicSharedMemorySize, GEMM_SMEM);
    const int ATTN_SMEM = ATT_Q_B + 2 * ATT_ST_B;      // 55296
    cudaFuncSetAttribute(attention_fp16_kernel, cudaFuncAttributeMaxDynamicSharedMemorySize, ATTN_SMEM);

    // 0) weight transpose -> fp16
    {
        dim3 tb(32, 8);
        transpose_fp16_kernel<<<dim3(32,  32), tb>>>(Wq, wgt + 0 * MEG, 1024, 1024);
        transpose_fp16_kernel<<<dim3(32,  32), tb>>>(Wk, wgt + 1 * MEG, 1024, 1024);
        transpose_fp16_kernel<<<dim3(32,  32), tb>>>(Wv, wgt + 2 * MEG, 1024, 1024);
        transpose_fp16_kernel<<<dim3(32,  32), tb>>>(Wo, wgt + 3 * MEG, 1024, 1024);
        transpose_fp16_kernel<<<dim3(128, 32), tb>>>(W1, wgt + 4 * MEG, 1024, 4096);
        transpose_fp16_kernel<<<dim3(32, 128), tb>>>(W2, wgt + 8 * MEG, 4096, 1024);
    }

    // 1) LN1 -> fp16
    layernorm_fp16_kernel<<<MROWS, 256>>>(x, g1, be1, ln);

    // 2) fused QKV projection -> fp16 [row][3072]
    {
        dim3 grid(QKVN / 128, MROWS / 128);
        gemm_fp16_kernel<0><<<grid, 256, GEMM_SMEM>>>(ln, wgt,
            nullptr, nullptr, nullptr, qkv, MROWS, QKVN, DMODEL);
    }

    // 3) causal attention -> att (fp16)
    {
        dim3 grid(SS / 128, BB * NHEADS);
        attention_fp16_kernel<<<grid, 256, ATTN_SMEM>>>(qkv, att);
    }

    // 4) output projection + residual(x) -> x2 (f32)
    {
        dim3 grid(DMODEL / 128, MROWS / 128);
        gemm_fp16_kernel<1><<<grid, 256, GEMM_SMEM>>>(att, wgt + 3 * MEG,
            nullptr, x, x2, nullptr, MROWS, DMODEL, DMODEL);
    }

    // 5) LN2 -> fp16
    layernorm_fp16_kernel<<<MROWS, 256>>>(x2, g2, be2, ln);

    // 6) FFN1: relu(h2 @ W1 + b1) -> fp16
    {
        dim3 grid(DFF / 128, MROWS / 128);
        gemm_fp16_kernel<2><<<grid, 256, GEMM_SMEM>>>(ln, wgt + 4 * MEG,
            b1, nullptr, nullptr, ff, MROWS, DFF, DMODEL);
    }

    // 7) FFN2: ff @ W2 + b2 + x2 -> out
    {
        dim3 grid(DMODEL / 128, MROWS / 128);
        gemm_fp16_kernel<3><<<grid, 256, GEMM_SMEM>>>(ff, wgt + 8 * MEG,
            b2, x2, out, nullptr, MROWS, DMODEL, DFF);
    }
}